// round 1
// baseline (speedup 1.0000x reference)
#include <cuda_runtime.h>
#include <cuda_bf16.h>

// Dims for MultiHeadAttention_3350074491182
#define BB   2
#define SS   2048
#define DD   768
#define HH   12
#define DK   64
#define BH   24            // BB*HH
#define MM   4096          // BB*SS

// Scratch (static device globals — no allocation)
__device__ float g_Q[BH * SS * DK];                 // [bh, s, dk]
__device__ float g_K[BH * SS * DK];
__device__ float g_V[BH * SS * DK];
__device__ float g_O[MM * DD];                      // merged heads [B*S, D]
__device__ float g_P[(size_t)BH * SS * SS];         // attention probs/scores

// ---------------------------------------------------------------------------
// Generic NT GEMM: C[m,n] = scale * sum_k A[m,k] * Bw[n,k] (+ bias[n])
// A: [M,K] row-major (lda=K), Bw: [N,K] row-major (ldb=K).
// 128x128 block tile, BK=8, 256 threads, 8x8 micro-tile per thread.
// headsplit=1: write C into [b, h, s, dk] layout (projection epilogue).
// blockIdx.z batches via strides sA/sB/sC.
// ---------------------------------------------------------------------------
__global__ __launch_bounds__(256) void gemm_nt(
    const float* __restrict__ A, const float* __restrict__ Bw,
    const float* __restrict__ bias, float* __restrict__ C,
    int K, long long sA, long long sB, long long sC,
    float scale, int headsplit, int ldc)
{
    const int z = blockIdx.z;
    A  += (long long)z * sA;
    Bw += (long long)z * sB;
    C  += (long long)z * sC;

    const int m0 = blockIdx.x * 128;
    const int n0 = blockIdx.y * 128;

    __shared__ float As[8][128];
    __shared__ float Bs[8][128];

    const int tid  = threadIdx.x;
    const int ty   = tid >> 4;        // 0..15 (row groups)
    const int tx   = tid & 15;        // 0..15 (col groups)
    const int lrow = tid >> 1;        // 0..127
    const int lcol = (tid & 1) * 4;   // 0 or 4

    const float* Ap = A  + (long long)(m0 + lrow) * K + lcol;
    const float* Bp = Bw + (long long)(n0 + lrow) * K + lcol;

    float acc[8][8];
#pragma unroll
    for (int i = 0; i < 8; i++)
#pragma unroll
        for (int j = 0; j < 8; j++) acc[i][j] = 0.f;

    for (int k0 = 0; k0 < K; k0 += 8) {
        float4 a = *(const float4*)(Ap + k0);
        float4 b = *(const float4*)(Bp + k0);
        As[lcol + 0][lrow] = a.x; As[lcol + 1][lrow] = a.y;
        As[lcol + 2][lrow] = a.z; As[lcol + 3][lrow] = a.w;
        Bs[lcol + 0][lrow] = b.x; Bs[lcol + 1][lrow] = b.y;
        Bs[lcol + 2][lrow] = b.z; Bs[lcol + 3][lrow] = b.w;
        __syncthreads();

#pragma unroll
        for (int kk = 0; kk < 8; kk++) {
            float af[8], bf[8];
#pragma unroll
            for (int i = 0; i < 4; i++) {
                af[i]     = As[kk][ty * 4 + i];
                af[4 + i] = As[kk][64 + ty * 4 + i];
            }
#pragma unroll
            for (int j = 0; j < 4; j++) {
                bf[j]     = Bs[kk][tx * 4 + j];
                bf[4 + j] = Bs[kk][64 + tx * 4 + j];
            }
#pragma unroll
            for (int i = 0; i < 8; i++)
#pragma unroll
                for (int j = 0; j < 8; j++)
                    acc[i][j] = fmaf(af[i], bf[j], acc[i][j]);
        }
        __syncthreads();
    }

#pragma unroll
    for (int i = 0; i < 8; i++) {
        const int row = m0 + ((i < 4) ? (ty * 4 + i) : (64 + ty * 4 + i - 4));
#pragma unroll
        for (int j = 0; j < 8; j++) {
            const int col = n0 + ((j < 4) ? (tx * 4 + j) : (64 + tx * 4 + j - 4));
            float val = acc[i][j] * scale;
            if (bias) val += bias[col];
            if (!headsplit) {
                C[(long long)row * ldc + col] = val;
            } else {
                const int h  = col >> 6;      // col / DK
                const int dk = col & 63;
                const int b  = row >> 11;     // row / SS
                const int s  = row & 2047;
                C[((((long long)b * HH + h) * SS) + s) * DK + dk] = val;
            }
        }
    }
}

// ---------------------------------------------------------------------------
// Row softmax over g_P: one block (256 threads) per row of SS=2048.
// ---------------------------------------------------------------------------
__global__ __launch_bounds__(256) void softmax_rows()
{
    const size_t row = blockIdx.x;
    float* p = g_P + row * (size_t)SS;
    const int tid = threadIdx.x;

    float v[8];
    float mx = -3.4e38f;
#pragma unroll
    for (int i = 0; i < 8; i++) {
        v[i] = p[i * 256 + tid];
        mx = fmaxf(mx, v[i]);
    }
#pragma unroll
    for (int o = 16; o > 0; o >>= 1)
        mx = fmaxf(mx, __shfl_xor_sync(0xffffffffu, mx, o));

    __shared__ float sred[16];
    if ((tid & 31) == 0) sred[tid >> 5] = mx;
    __syncthreads();
    if (tid == 0) {
        float t = sred[0];
        for (int i = 1; i < 8; i++) t = fmaxf(t, sred[i]);
        sred[8] = t;
    }
    __syncthreads();
    mx = sred[8];

    float s = 0.f;
#pragma unroll
    for (int i = 0; i < 8; i++) {
        v[i] = __expf(v[i] - mx);
        s += v[i];
    }
#pragma unroll
    for (int o = 16; o > 0; o >>= 1)
        s += __shfl_xor_sync(0xffffffffu, s, o);
    __syncthreads();
    if ((tid & 31) == 0) sred[tid >> 5] = s;
    __syncthreads();
    if (tid == 0) {
        float t = 0.f;
        for (int i = 0; i < 8; i++) t += sred[i];
        sred[8] = 1.f / t;
    }
    __syncthreads();
    const float inv = sred[8];
#pragma unroll
    for (int i = 0; i < 8; i++) p[i * 256 + tid] = v[i] * inv;
}

// ---------------------------------------------------------------------------
// PV GEMM (NN): per head bh, O[s,d] = sum_j P[s,j] * V[j,d].
// BM=128, BN=64 (=DK), BK=16, 256 threads, 8x4 micro-tile.
// Epilogue merges heads: g_O[(b*SS+s)*DD + h*DK + d].
// ---------------------------------------------------------------------------
__global__ __launch_bounds__(256) void gemm_pv()
{
    const int bh = blockIdx.z;
    const int b  = bh / HH;
    const int h  = bh % HH;
    const float* Pb = g_P + (size_t)bh * SS * SS;
    const float* Vb = g_V + (size_t)bh * SS * DK;
    const int m0 = blockIdx.x * 128;

    __shared__ float Ps[16][128];
    __shared__ __align__(16) float Vs[16][64];

    const int tid = threadIdx.x;
    const int ty  = tid >> 4;         // 0..15
    const int tx  = tid & 15;         // 0..15
    const int pr  = tid >> 2;         // 0..63
    const int pc  = (tid & 3) * 4;    // 0,4,8,12
    const int vr  = tid >> 4;         // 0..15
    const int vc  = (tid & 15) * 4;   // 0..60

    float acc[8][4];
#pragma unroll
    for (int i = 0; i < 8; i++)
#pragma unroll
        for (int j = 0; j < 4; j++) acc[i][j] = 0.f;

    for (int k0 = 0; k0 < SS; k0 += 16) {
        float4 p0 = *(const float4*)(Pb + (size_t)(m0 + pr) * SS + k0 + pc);
        float4 p1 = *(const float4*)(Pb + (size_t)(m0 + 64 + pr) * SS + k0 + pc);
        Ps[pc + 0][pr] = p0.x; Ps[pc + 1][pr] = p0.y;
        Ps[pc + 2][pr] = p0.z; Ps[pc + 3][pr] = p0.w;
        Ps[pc + 0][64 + pr] = p1.x; Ps[pc + 1][64 + pr] = p1.y;
        Ps[pc + 2][64 + pr] = p1.z; Ps[pc + 3][64 + pr] = p1.w;
        *(float4*)&Vs[vr][vc] = *(const float4*)(Vb + (size_t)(k0 + vr) * DK + vc);
        __syncthreads();

#pragma unroll
        for (int kk = 0; kk < 16; kk++) {
            float af[8], bf[4];
#pragma unroll
            for (int i = 0; i < 4; i++) {
                af[i]     = Ps[kk][ty * 4 + i];
                af[4 + i] = Ps[kk][64 + ty * 4 + i];
            }
#pragma unroll
            for (int j = 0; j < 4; j++) bf[j] = Vs[kk][tx * 4 + j];
#pragma unroll
            for (int i = 0; i < 8; i++)
#pragma unroll
                for (int j = 0; j < 4; j++)
                    acc[i][j] = fmaf(af[i], bf[j], acc[i][j]);
        }
        __syncthreads();
    }

#pragma unroll
    for (int i = 0; i < 8; i++) {
        const int s = m0 + ((i < 4) ? (ty * 4 + i) : (64 + ty * 4 + i - 4));
#pragma unroll
        for (int j = 0; j < 4; j++) {
            const int d = tx * 4 + j;
            g_O[((size_t)(b * SS + s)) * DD + h * DK + d] = acc[i][j];
        }
    }
}

// ---------------------------------------------------------------------------
// kernel_launch: 7 launches, all graph-capturable, no allocations.
// Input order per metadata: k, q, v, mask, wq, bq, wk, bk, wv, bv, wo, bo
// ---------------------------------------------------------------------------
extern "C" void kernel_launch(void* const* d_in, const int* in_sizes, int n_in,
                              void* d_out, int out_size)
{
    const float* k_in = (const float*)d_in[0];
    const float* q_in = (const float*)d_in[1];
    const float* v_in = (const float*)d_in[2];
    // d_in[3] = mask (no-op in reference)
    const float* wq = (const float*)d_in[4];
    const float* bq = (const float*)d_in[5];
    const float* wk = (const float*)d_in[6];
    const float* bk = (const float*)d_in[7];
    const float* wv = (const float*)d_in[8];
    const float* bv = (const float*)d_in[9];
    const float* wo = (const float*)d_in[10];
    const float* bo = (const float*)d_in[11];
    float* out = (float*)d_out;

    float *pQ, *pK, *pV, *pO, *pP;
    cudaGetSymbolAddress((void**)&pQ, g_Q);
    cudaGetSymbolAddress((void**)&pK, g_K);
    cudaGetSymbolAddress((void**)&pV, g_V);
    cudaGetSymbolAddress((void**)&pO, g_O);
    cudaGetSymbolAddress((void**)&pP, g_P);

    dim3 gproj(MM / 128, DD / 128, 1);    // 32 x 6
    // Q/K/V projections -> head-split layout
    gemm_nt<<<gproj, 256>>>(q_in, wq, bq, pQ, DD, 0, 0, 0, 1.f, 1, 0);
    gemm_nt<<<gproj, 256>>>(k_in, wk, bk, pK, DD, 0, 0, 0, 1.f, 1, 0);
    gemm_nt<<<gproj, 256>>>(v_in, wv, bv, pV, DD, 0, 0, 0, 1.f, 1, 0);

    // Scores: P[bh] = (Q[bh] @ K[bh]^T) / 8
    dim3 gsc(SS / 128, SS / 128, BH);     // 16 x 16 x 24
    gemm_nt<<<gsc, 256>>>(pQ, pK, nullptr, pP, DK,
                          (long long)SS * DK, (long long)SS * DK,
                          (long long)SS * SS, 0.125f, 0, SS);

    // Softmax over each row of P
    softmax_rows<<<BH * SS, 256>>>();

    // O[bh] = P[bh] @ V[bh], merged-head layout
    gemm_pv<<<dim3(SS / 128, 1, BH), 256>>>();

    // Final projection into d_out [B*S, D]
    gemm_nt<<<gproj, 256>>>(pO, wo, bo, out, DD, 0, 0, 0, 1.f, 0, DD);
}

// round 3
// speedup vs baseline: 1.9198x; 1.9198x over previous
#include <cuda_runtime.h>
#include <cuda_bf16.h>
#include <cstdint>

// ─────────────────────────────────────────────────────────────────────────────
// Dims
// ─────────────────────────────────────────────────────────────────────────────
#define BB 2
#define SS 2048
#define DD 768
#define HH 12
#define DK 64
#define BH 24           // BB*HH
#define MM 4096         // BB*SS

// ─────────────────────────────────────────────────────────────────────────────
// Scratch (static device globals — no allocation)
// ─────────────────────────────────────────────────────────────────────────────
__device__ __nv_bfloat16 g_xqh[MM * DD], g_xql[MM * DD];
__device__ __nv_bfloat16 g_xkh[MM * DD], g_xkl[MM * DD];
__device__ __nv_bfloat16 g_xvh[MM * DD], g_xvl[MM * DD];
__device__ __nv_bfloat16 g_wqh[DD * DD], g_wql[DD * DD];
__device__ __nv_bfloat16 g_wkh[DD * DD], g_wkl[DD * DD];
__device__ __nv_bfloat16 g_wvh[DD * DD], g_wvl[DD * DD];
__device__ __nv_bfloat16 g_woh[DD * DD], g_wol[DD * DD];
__device__ __nv_bfloat16 g_Qh[BH * SS * DK], g_Ql[BH * SS * DK];
__device__ __nv_bfloat16 g_Kh[BH * SS * DK], g_Kl[BH * SS * DK];
__device__ __nv_bfloat16 g_Vth[BH * SS * DK], g_Vtl[BH * SS * DK];   // [bh, dk, s]
__device__ float         g_P [(size_t)BH * SS * SS];
__device__ __nv_bfloat16 g_Ph[(size_t)BH * SS * SS];
__device__ __nv_bfloat16 g_Pl[(size_t)BH * SS * SS];
__device__ __nv_bfloat16 g_Oh[MM * DD], g_Ol[MM * DD];

// ─────────────────────────────────────────────────────────────────────────────
// PTX helpers (baseline ISA only — no tcgen05; harness targets sm_103 non-'a')
// ─────────────────────────────────────────────────────────────────────────────
__device__ __forceinline__ uint32_t smem_u32(const void* p) {
    uint32_t a;
    asm("{ .reg .u64 t; cvta.to.shared.u64 t, %1; cvt.u32.u64 %0, t; }"
        : "=r"(a) : "l"(p));
    return a;
}

__device__ __forceinline__ void cp_async16(uint32_t saddr, const void* gaddr) {
    asm volatile("cp.async.ca.shared.global [%0], [%1], 16;"
                 :: "r"(saddr), "l"(gaddr));
}
__device__ __forceinline__ void cp_commit() {
    asm volatile("cp.async.commit_group;");
}
__device__ __forceinline__ void cp_wait_all() {
    asm volatile("cp.async.wait_group 0;");
}

__device__ __forceinline__ void ldm_x4(uint32_t addr, uint32_t* r) {
    asm volatile("ldmatrix.sync.aligned.m8n8.x4.shared.b16 {%0,%1,%2,%3}, [%4];"
                 : "=r"(r[0]), "=r"(r[1]), "=r"(r[2]), "=r"(r[3]) : "r"(addr));
}
__device__ __forceinline__ void ldm_x2(uint32_t addr, uint32_t* r) {
    asm volatile("ldmatrix.sync.aligned.m8n8.x2.shared.b16 {%0,%1}, [%2];"
                 : "=r"(r[0]), "=r"(r[1]) : "r"(addr));
}

__device__ __forceinline__ void mma16816(float* c, const uint32_t* a, const uint32_t* b) {
    asm volatile(
        "mma.sync.aligned.m16n8k16.row.col.f32.bf16.bf16.f32 "
        "{%0,%1,%2,%3}, {%4,%5,%6,%7}, {%8,%9}, {%0,%1,%2,%3};"
        : "+f"(c[0]), "+f"(c[1]), "+f"(c[2]), "+f"(c[3])
        : "r"(a[0]), "r"(a[1]), "r"(a[2]), "r"(a[3]), "r"(b[0]), "r"(b[1]));
}

__device__ __forceinline__ void split2(float x, __nv_bfloat16& h, __nv_bfloat16& l) {
    h = __float2bfloat16(x);
    l = __float2bfloat16(x - __bfloat162float(h));
}

// ─────────────────────────────────────────────────────────────────────────────
// Warp-MMA GEMM (NT): C[m,n] = scale * sum_k (Ah+Al)[m,k]*(Bh+Bl)[n,k] (+bias)
// 3 bf16 mma passes (hh + hl + lh), fp32 accumulators in registers.
// BM=128, BK=32, 256 threads. 2-stage cp.async pipeline.
// Smem rows: 32 bf16 + 16B pad = 80B stride (conflict-free ldmatrix).
// mode 0: fp32 -> Cf[z*sC + row*ldc + col]
// mode 1: bf16 hi/lo head-split      -> Ch/Cl[((b*H+h)*SS+s)*DK+dk]
// mode 2: bf16 hi/lo head-split+T    -> Ch/Cl[((b*H+h)*DK+dk)*SS+s]
// mode 3: bf16 hi/lo merged-head (z=bh) -> Ch/Cl[(b*SS+s)*DD + h*DK + col]
// ─────────────────────────────────────────────────────────────────────────────
template <int BN>
__global__ void __launch_bounds__(256) wgemm(
    const __nv_bfloat16* __restrict__ Ah, const __nv_bfloat16* __restrict__ Al,
    int lda, long long sA,
    const __nv_bfloat16* __restrict__ Bh, const __nv_bfloat16* __restrict__ Bl,
    int ldb, long long sB,
    int K, float scale, const float* __restrict__ bias, int mode,
    float* __restrict__ Cf, __nv_bfloat16* __restrict__ Ch,
    __nv_bfloat16* __restrict__ Cl, int ldc, long long sC)
{
    constexpr int BM = 128;
    constexpr int WARPS_M = (BN == 128) ? 2 : 4;
    constexpr int WM = BM / WARPS_M;      // 64 | 32
    constexpr int WN = BN / (8 / WARPS_M);// 32 | 32
    constexpr int MT = WM / 16;           // 4  | 2
    constexpr int NT = WN / 8;            // 4

    constexpr int LDSB  = 80;             // bytes per 32-bf16 smem row (+16B pad)
    constexpr int ATILE = BM * LDSB;      // 10240
    constexpr int BTILE = BN * LDSB;
    constexpr int STAGE = 2 * ATILE + 2 * BTILE;

    extern __shared__ __align__(16) char smem[];
    const uint32_t sb = smem_u32(smem);

    const int tid  = threadIdx.x;
    const int w    = tid >> 5;
    const int lane = tid & 31;
    const int z    = blockIdx.z;
    const int m0   = blockIdx.x * BM;
    const int n0   = blockIdx.y * BN;

    const int wm0 = (w % WARPS_M) * WM;
    const int wn0 = (w / WARPS_M) * WN;

    const __nv_bfloat16* pAh = Ah + (size_t)z * sA + (size_t)m0 * lda;
    const __nv_bfloat16* pAl = Al + (size_t)z * sA + (size_t)m0 * lda;
    const __nv_bfloat16* pBh = Bh + (size_t)z * sB + (size_t)n0 * ldb;
    const __nv_bfloat16* pBl = Bl + (size_t)z * sB + (size_t)n0 * ldb;

    // ---- stage loader (cp.async, 16B chunks) ----
    auto load_stage = [&](int st, int k0) {
        const uint32_t s0 = sb + st * STAGE;
        // A hi/lo: BM*4 chunks each
        for (int c = tid; c < BM * 4; c += 256) {
            const int r = c >> 2, kc = c & 3;
            cp_async16(s0 + r * LDSB + kc * 16,            pAh + (size_t)r * lda + k0 + kc * 8);
            cp_async16(s0 + ATILE + r * LDSB + kc * 16,    pAl + (size_t)r * lda + k0 + kc * 8);
        }
        // B hi/lo: BN*4 chunks each
        for (int c = tid; c < BN * 4; c += 256) {
            const int r = c >> 2, kc = c & 3;
            cp_async16(s0 + 2 * ATILE + r * LDSB + kc * 16,         pBh + (size_t)r * ldb + k0 + kc * 8);
            cp_async16(s0 + 2 * ATILE + BTILE + r * LDSB + kc * 16, pBl + (size_t)r * ldb + k0 + kc * 8);
        }
        cp_commit();
    };

    float acc[MT][NT][4];
#pragma unroll
    for (int i = 0; i < MT; i++)
#pragma unroll
        for (int j = 0; j < NT; j++)
#pragma unroll
            for (int q = 0; q < 4; q++) acc[i][j][q] = 0.f;

    const int niter = K >> 5;   // BK=32
    load_stage(0, 0);

    for (int it = 0; it < niter; it++) {
        cp_wait_all();
        __syncthreads();
        if (it + 1 < niter) load_stage((it + 1) & 1, (it + 1) << 5);

        const uint32_t s0  = sb + (it & 1) * STAGE;
        const uint32_t sAh = s0;
        const uint32_t sAl = s0 + ATILE;
        const uint32_t sBh = s0 + 2 * ATILE;
        const uint32_t sBl = sBh + BTILE;

#pragma unroll
        for (int ks = 0; ks < 2; ks++) {
            uint32_t fAh[MT][4], fAl[MT][4], fBh[NT][2], fBl[NT][2];
            const uint32_t acol = ks * 32 + (lane >> 4) * 16;            // bytes
            const uint32_t bcol = ks * 32 + ((lane >> 3) & 1) * 16;      // bytes
#pragma unroll
            for (int mi = 0; mi < MT; mi++) {
                const uint32_t ar = (wm0 + mi * 16 + (lane & 15)) * LDSB + acol;
                ldm_x4(sAh + ar, fAh[mi]);
                ldm_x4(sAl + ar, fAl[mi]);
            }
#pragma unroll
            for (int ni = 0; ni < NT; ni++) {
                const uint32_t br = (wn0 + ni * 8 + (lane & 7)) * LDSB + bcol;
                ldm_x2(sBh + br, fBh[ni]);
                ldm_x2(sBl + br, fBl[ni]);
            }
#pragma unroll
            for (int mi = 0; mi < MT; mi++)
#pragma unroll
                for (int ni = 0; ni < NT; ni++) {
                    mma16816(acc[mi][ni], fAh[mi], fBh[ni]);
                    mma16816(acc[mi][ni], fAh[mi], fBl[ni]);
                    mma16816(acc[mi][ni], fAl[mi], fBh[ni]);
                }
        }
        __syncthreads();
    }

    // ---- epilogue ----
    const int qr = lane >> 2;            // 0..7
    const int qc = (lane & 3) * 2;       // 0,2,4,6
#pragma unroll
    for (int mi = 0; mi < MT; mi++)
#pragma unroll
        for (int ni = 0; ni < NT; ni++)
#pragma unroll
            for (int h2 = 0; h2 < 2; h2++) {
                const int row = m0 + wm0 + mi * 16 + qr + h2 * 8;
                const int col = n0 + wn0 + ni * 8 + qc;
                float v0 = acc[mi][ni][h2 * 2 + 0] * scale;
                float v1 = acc[mi][ni][h2 * 2 + 1] * scale;
                if (bias) { v0 += bias[col]; v1 += bias[col + 1]; }
                if (mode == 0) {
                    float2 fv = make_float2(v0, v1);
                    *(float2*)&Cf[(size_t)z * sC + (size_t)row * ldc + col] = fv;
                } else if (mode == 1) {
                    const int b = row >> 11, s = row & 2047, h = col >> 6, dk = col & 63;
                    const size_t o = ((((size_t)b * HH + h) * SS) + s) * DK + dk;
                    __nv_bfloat16 h0, l0, h1, l1;
                    split2(v0, h0, l0); split2(v1, h1, l1);
                    *(__nv_bfloat162*)&Ch[o] = __nv_bfloat162(h0, h1);
                    *(__nv_bfloat162*)&Cl[o] = __nv_bfloat162(l0, l1);
                } else if (mode == 2) {
                    const int b = row >> 11, s = row & 2047, h = col >> 6, dk = col & 63;
                    const size_t o = ((((size_t)b * HH + h) * DK) + dk) * SS + s;
                    __nv_bfloat16 h0, l0, h1, l1;
                    split2(v0, h0, l0); split2(v1, h1, l1);
                    Ch[o] = h0; Cl[o] = l0;
                    Ch[o + SS] = h1; Cl[o + SS] = l1;
                } else {   // mode 3: z = bh
                    const int b = z / HH, h = z % HH;
                    const size_t o = ((size_t)(b * SS + row)) * DD + h * DK + col;
                    __nv_bfloat16 h0, l0, h1, l1;
                    split2(v0, h0, l0); split2(v1, h1, l1);
                    *(__nv_bfloat162*)&Ch[o] = __nv_bfloat162(h0, h1);
                    *(__nv_bfloat162*)&Cl[o] = __nv_bfloat162(l0, l1);
                }
            }
}

// ─────────────────────────────────────────────────────────────────────────────
// Elementwise fp32 -> bf16 hi/lo split
// ─────────────────────────────────────────────────────────────────────────────
__global__ void __launch_bounds__(256) split_f32(
    const float* __restrict__ s, __nv_bfloat16* __restrict__ h,
    __nv_bfloat16* __restrict__ l, int n)
{
    int i = blockIdx.x * 256 + threadIdx.x;
    if (i < n) {
        float x = s[i];
        __nv_bfloat16 hi, lo; split2(x, hi, lo);
        h[i] = hi; l[i] = lo;
    }
}

// ─────────────────────────────────────────────────────────────────────────────
// Row softmax: read fp32 g_P row, write bf16 hi/lo planes g_Ph/g_Pl.
// ─────────────────────────────────────────────────────────────────────────────
__global__ void __launch_bounds__(256) softmax_split()
{
    const size_t row = blockIdx.x;
    const float* p = g_P + row * (size_t)SS;
    __nv_bfloat16* ph = g_Ph + row * (size_t)SS;
    __nv_bfloat16* pl = g_Pl + row * (size_t)SS;
    const int tid = threadIdx.x;

    float v[8];
    float mx = -3.4e38f;
#pragma unroll
    for (int i = 0; i < 8; i++) {
        v[i] = p[i * 256 + tid];
        mx = fmaxf(mx, v[i]);
    }
#pragma unroll
    for (int o = 16; o > 0; o >>= 1)
        mx = fmaxf(mx, __shfl_xor_sync(0xffffffffu, mx, o));

    __shared__ float sred[16];
    if ((tid & 31) == 0) sred[tid >> 5] = mx;
    __syncthreads();
    if (tid == 0) {
        float t = sred[0];
        for (int i = 1; i < 8; i++) t = fmaxf(t, sred[i]);
        sred[8] = t;
    }
    __syncthreads();
    mx = sred[8];

    float s = 0.f;
#pragma unroll
    for (int i = 0; i < 8; i++) {
        v[i] = __expf(v[i] - mx);
        s += v[i];
    }
#pragma unroll
    for (int o = 16; o > 0; o >>= 1)
        s += __shfl_xor_sync(0xffffffffu, s, o);
    __syncthreads();
    if ((tid & 31) == 0) sred[tid >> 5] = s;
    __syncthreads();
    if (tid == 0) {
        float t = 0.f;
        for (int i = 0; i < 8; i++) t += sred[i];
        sred[8] = 1.f / t;
    }
    __syncthreads();
    const float inv = sred[8];
#pragma unroll
    for (int i = 0; i < 8; i++) {
        float e = v[i] * inv;
        __nv_bfloat16 hi, lo; split2(e, hi, lo);
        ph[i * 256 + tid] = hi;
        pl[i * 256 + tid] = lo;
    }
}

// ─────────────────────────────────────────────────────────────────────────────
// kernel_launch
// Input order: k, q, v, mask, wq, bq, wk, bk, wv, bv, wo, bo
// ─────────────────────────────────────────────────────────────────────────────
extern "C" void kernel_launch(void* const* d_in, const int* in_sizes, int n_in,
                              void* d_out, int out_size)
{
    const float* k_in = (const float*)d_in[0];
    const float* q_in = (const float*)d_in[1];
    const float* v_in = (const float*)d_in[2];
    const float* wq = (const float*)d_in[4];
    const float* bq = (const float*)d_in[5];
    const float* wk = (const float*)d_in[6];
    const float* bk = (const float*)d_in[7];
    const float* wv = (const float*)d_in[8];
    const float* bv = (const float*)d_in[9];
    const float* wo = (const float*)d_in[10];
    const float* bo = (const float*)d_in[11];
    float* out = (float*)d_out;

    __nv_bfloat16 *xqh, *xql, *xkh, *xkl, *xvh, *xvl;
    __nv_bfloat16 *wqh, *wql, *wkh, *wkl, *wvh, *wvl, *woh, *wol;
    __nv_bfloat16 *Qh, *Ql, *Kh, *Kl, *Vth, *Vtl, *Ph, *Pl, *Oh, *Ol;
    float* P;
    cudaGetSymbolAddress((void**)&xqh, g_xqh); cudaGetSymbolAddress((void**)&xql, g_xql);
    cudaGetSymbolAddress((void**)&xkh, g_xkh); cudaGetSymbolAddress((void**)&xkl, g_xkl);
    cudaGetSymbolAddress((void**)&xvh, g_xvh); cudaGetSymbolAddress((void**)&xvl, g_xvl);
    cudaGetSymbolAddress((void**)&wqh, g_wqh); cudaGetSymbolAddress((void**)&wql, g_wql);
    cudaGetSymbolAddress((void**)&wkh, g_wkh); cudaGetSymbolAddress((void**)&wkl, g_wkl);
    cudaGetSymbolAddress((void**)&wvh, g_wvh); cudaGetSymbolAddress((void**)&wvl, g_wvl);
    cudaGetSymbolAddress((void**)&woh, g_woh); cudaGetSymbolAddress((void**)&wol, g_wol);
    cudaGetSymbolAddress((void**)&Qh,  g_Qh);  cudaGetSymbolAddress((void**)&Ql,  g_Ql);
    cudaGetSymbolAddress((void**)&Kh,  g_Kh);  cudaGetSymbolAddress((void**)&Kl,  g_Kl);
    cudaGetSymbolAddress((void**)&Vth, g_Vth); cudaGetSymbolAddress((void**)&Vtl, g_Vtl);
    cudaGetSymbolAddress((void**)&Ph,  g_Ph);  cudaGetSymbolAddress((void**)&Pl,  g_Pl);
    cudaGetSymbolAddress((void**)&Oh,  g_Oh);  cudaGetSymbolAddress((void**)&Ol,  g_Ol);
    cudaGetSymbolAddress((void**)&P,   g_P);

    // Smem opt-in: BN=128 -> 81920 B, BN=64 -> 61440 B
    cudaFuncSetAttribute(wgemm<128>, cudaFuncAttributeMaxDynamicSharedMemorySize, 81920);
    cudaFuncSetAttribute(wgemm<64>,  cudaFuncAttributeMaxDynamicSharedMemorySize, 61440);

    const int nAct = MM * DD, nW = DD * DD;

    // 1. fp32 -> bf16 hi/lo splits
    split_f32<<<(nAct + 255) / 256, 256>>>(q_in, xqh, xql, nAct);
    split_f32<<<(nAct + 255) / 256, 256>>>(k_in, xkh, xkl, nAct);
    split_f32<<<(nAct + 255) / 256, 256>>>(v_in, xvh, xvl, nAct);
    split_f32<<<(nW + 255) / 256, 256>>>(wq, wqh, wql, nW);
    split_f32<<<(nW + 255) / 256, 256>>>(wk, wkh, wkl, nW);
    split_f32<<<(nW + 255) / 256, 256>>>(wv, wvh, wvl, nW);
    split_f32<<<(nW + 255) / 256, 256>>>(wo, woh, wol, nW);

    // 2. Projections (M=4096, N=768, K=768)
    dim3 gproj(MM / 128, DD / 128, 1);
    wgemm<128><<<gproj, 256, 81920>>>(xqh, xql, DD, 0, wqh, wql, DD, 0,
                                      DD, 1.f, bq, 1, nullptr, Qh, Ql, 0, 0);
    wgemm<128><<<gproj, 256, 81920>>>(xkh, xkl, DD, 0, wkh, wkl, DD, 0,
                                      DD, 1.f, bk, 1, nullptr, Kh, Kl, 0, 0);
    wgemm<128><<<gproj, 256, 81920>>>(xvh, xvl, DD, 0, wvh, wvl, DD, 0,
                                      DD, 1.f, bv, 2, nullptr, Vth, Vtl, 0, 0);

    // 3. Scores: P[bh] = (Q[bh] @ K[bh]^T) / 8  (M=N=2048, K=64)
    dim3 gsc(SS / 128, SS / 128, BH);
    wgemm<128><<<gsc, 256, 81920>>>(Qh, Ql, DK, (long long)SS * DK,
                                    Kh, Kl, DK, (long long)SS * DK,
                                    DK, 0.125f, nullptr, 0,
                                    P, nullptr, nullptr, SS, (long long)SS * SS);

    // 4. Softmax -> bf16 hi/lo planes
    softmax_split<<<BH * SS, 256>>>();

    // 5. PV: O[bh] = P[bh] @ V[bh]^T_layout  (M=2048, N=64, K=2048)
    dim3 gpv(SS / 128, 1, BH);
    wgemm<64><<<gpv, 256, 61440>>>(Ph, Pl, SS, (long long)SS * SS,
                                   Vth, Vtl, SS, (long long)DK * SS,
                                   SS, 1.f, nullptr, 3,
                                   nullptr, Oh, Ol, 0, 0);

    // 6. Output projection into d_out (M=4096, N=768, K=768)
    wgemm<128><<<gproj, 256, 81920>>>(Oh, Ol, DD, 0, woh, wol, DD, 0,
                                      DD, 1.f, bo, 0, out, nullptr, nullptr, DD, 0);
}

// round 4
// speedup vs baseline: 2.7377x; 1.4260x over previous
#include <cuda_runtime.h>
#include <cuda_bf16.h>
#include <cstdint>

// ─────────────────────────────────────────────────────────────────────────────
// Dims
// ─────────────────────────────────────────────────────────────────────────────
#define BB 2
#define SS 2048
#define DD 768
#define HH 12
#define DK 64
#define BH 24           // BB*HH
#define MM 4096         // BB*SS

// ─────────────────────────────────────────────────────────────────────────────
// Scratch (static device globals — no allocation)
// ─────────────────────────────────────────────────────────────────────────────
__device__ __nv_bfloat16 g_xqh[MM * DD], g_xql[MM * DD];
__device__ __nv_bfloat16 g_xkh[MM * DD], g_xkl[MM * DD];
__device__ __nv_bfloat16 g_xvh[MM * DD], g_xvl[MM * DD];
__device__ __nv_bfloat16 g_wqh[DD * DD], g_wql[DD * DD];
__device__ __nv_bfloat16 g_wkh[DD * DD], g_wkl[DD * DD];
__device__ __nv_bfloat16 g_wvh[DD * DD], g_wvl[DD * DD];
__device__ __nv_bfloat16 g_woh[DD * DD], g_wol[DD * DD];
__device__ __nv_bfloat16 g_Qh[BH * SS * DK], g_Ql[BH * SS * DK];
__device__ __nv_bfloat16 g_Kh[BH * SS * DK], g_Kl[BH * SS * DK];
__device__ __nv_bfloat16 g_Vth[BH * SS * DK], g_Vtl[BH * SS * DK];   // [bh, dk, s]
__device__ __nv_bfloat16 g_Oh[MM * DD], g_Ol[MM * DD];

// ─────────────────────────────────────────────────────────────────────────────
// PTX helpers (baseline ISA only — harness targets sm_103 non-'a', no tcgen05)
// ─────────────────────────────────────────────────────────────────────────────
__device__ __forceinline__ uint32_t smem_u32(const void* p) {
    uint32_t a;
    asm("{ .reg .u64 t; cvta.to.shared.u64 t, %1; cvt.u32.u64 %0, t; }"
        : "=r"(a) : "l"(p));
    return a;
}

__device__ __forceinline__ void cp_async16(uint32_t saddr, const void* gaddr) {
    asm volatile("cp.async.ca.shared.global [%0], [%1], 16;"
                 :: "r"(saddr), "l"(gaddr));
}
__device__ __forceinline__ void cp_commit() {
    asm volatile("cp.async.commit_group;");
}
__device__ __forceinline__ void cp_wait_all() {
    asm volatile("cp.async.wait_group 0;");
}
__device__ __forceinline__ void cp_wait_1() {
    asm volatile("cp.async.wait_group 1;");
}

__device__ __forceinline__ void ldm_x4(uint32_t addr, uint32_t* r) {
    asm volatile("ldmatrix.sync.aligned.m8n8.x4.shared.b16 {%0,%1,%2,%3}, [%4];"
                 : "=r"(r[0]), "=r"(r[1]), "=r"(r[2]), "=r"(r[3]) : "r"(addr));
}
__device__ __forceinline__ void ldm_x2(uint32_t addr, uint32_t* r) {
    asm volatile("ldmatrix.sync.aligned.m8n8.x2.shared.b16 {%0,%1}, [%2];"
                 : "=r"(r[0]), "=r"(r[1]) : "r"(addr));
}

__device__ __forceinline__ void mma16816(float* c, const uint32_t* a, const uint32_t* b) {
    asm volatile(
        "mma.sync.aligned.m16n8k16.row.col.f32.bf16.bf16.f32 "
        "{%0,%1,%2,%3}, {%4,%5,%6,%7}, {%8,%9}, {%0,%1,%2,%3};"
        : "+f"(c[0]), "+f"(c[1]), "+f"(c[2]), "+f"(c[3])
        : "r"(a[0]), "r"(a[1]), "r"(a[2]), "r"(a[3]), "r"(b[0]), "r"(b[1]));
}

__device__ __forceinline__ void split2(float x, __nv_bfloat16& h, __nv_bfloat16& l) {
    h = __float2bfloat16(x);
    l = __float2bfloat16(x - __bfloat162float(h));
}

__device__ __forceinline__ uint32_t pack_bf2(__nv_bfloat16 a, __nv_bfloat16 b) {
    __nv_bfloat162 t(a, b);          // a in low half
    return *(uint32_t*)&t;
}

// ─────────────────────────────────────────────────────────────────────────────
// Warp-MMA GEMM (NT) — unchanged from Round 3 (projections + output proj).
// mode 0: fp32 C; mode 1: bf16 hi/lo head-split; mode 2: head-split transposed.
// ─────────────────────────────────────────────────────────────────────────────
template <int BN>
__global__ void __launch_bounds__(256) wgemm(
    const __nv_bfloat16* __restrict__ Ah, const __nv_bfloat16* __restrict__ Al,
    int lda, long long sA,
    const __nv_bfloat16* __restrict__ Bh, const __nv_bfloat16* __restrict__ Bl,
    int ldb, long long sB,
    int K, float scale, const float* __restrict__ bias, int mode,
    float* __restrict__ Cf, __nv_bfloat16* __restrict__ Ch,
    __nv_bfloat16* __restrict__ Cl, int ldc, long long sC)
{
    constexpr int BM = 128;
    constexpr int WARPS_M = (BN == 128) ? 2 : 4;
    constexpr int WM = BM / WARPS_M;
    constexpr int WN = BN / (8 / WARPS_M);
    constexpr int MT = WM / 16;
    constexpr int NT = WN / 8;

    constexpr int LDSB  = 80;
    constexpr int ATILE = BM * LDSB;
    constexpr int BTILE = BN * LDSB;
    constexpr int STAGE = 2 * ATILE + 2 * BTILE;

    extern __shared__ __align__(16) char smem[];
    const uint32_t sb = smem_u32(smem);

    const int tid  = threadIdx.x;
    const int w    = tid >> 5;
    const int lane = tid & 31;
    const int z    = blockIdx.z;
    const int m0   = blockIdx.x * BM;
    const int n0   = blockIdx.y * BN;

    const int wm0 = (w % WARPS_M) * WM;
    const int wn0 = (w / WARPS_M) * WN;

    const __nv_bfloat16* pAh = Ah + (size_t)z * sA + (size_t)m0 * lda;
    const __nv_bfloat16* pAl = Al + (size_t)z * sA + (size_t)m0 * lda;
    const __nv_bfloat16* pBh = Bh + (size_t)z * sB + (size_t)n0 * ldb;
    const __nv_bfloat16* pBl = Bl + (size_t)z * sB + (size_t)n0 * ldb;

    auto load_stage = [&](int st, int k0) {
        const uint32_t s0 = sb + st * STAGE;
        for (int c = tid; c < BM * 4; c += 256) {
            const int r = c >> 2, kc = c & 3;
            cp_async16(s0 + r * LDSB + kc * 16,         pAh + (size_t)r * lda + k0 + kc * 8);
            cp_async16(s0 + ATILE + r * LDSB + kc * 16, pAl + (size_t)r * lda + k0 + kc * 8);
        }
        for (int c = tid; c < BN * 4; c += 256) {
            const int r = c >> 2, kc = c & 3;
            cp_async16(s0 + 2 * ATILE + r * LDSB + kc * 16,         pBh + (size_t)r * ldb + k0 + kc * 8);
            cp_async16(s0 + 2 * ATILE + BTILE + r * LDSB + kc * 16, pBl + (size_t)r * ldb + k0 + kc * 8);
        }
        cp_commit();
    };

    float acc[MT][NT][4];
#pragma unroll
    for (int i = 0; i < MT; i++)
#pragma unroll
        for (int j = 0; j < NT; j++)
#pragma unroll
            for (int q = 0; q < 4; q++) acc[i][j][q] = 0.f;

    const int niter = K >> 5;
    load_stage(0, 0);

    for (int it = 0; it < niter; it++) {
        cp_wait_all();
        __syncthreads();
        if (it + 1 < niter) load_stage((it + 1) & 1, (it + 1) << 5);

        const uint32_t s0  = sb + (it & 1) * STAGE;
        const uint32_t sAh = s0;
        const uint32_t sAl = s0 + ATILE;
        const uint32_t sBh = s0 + 2 * ATILE;
        const uint32_t sBl = sBh + BTILE;

#pragma unroll
        for (int ks = 0; ks < 2; ks++) {
            uint32_t fAh[MT][4], fAl[MT][4], fBh[NT][2], fBl[NT][2];
            const uint32_t acol = ks * 32 + (lane >> 4) * 16;
            const uint32_t bcol = ks * 32 + ((lane >> 3) & 1) * 16;
#pragma unroll
            for (int mi = 0; mi < MT; mi++) {
                const uint32_t ar = (wm0 + mi * 16 + (lane & 15)) * LDSB + acol;
                ldm_x4(sAh + ar, fAh[mi]);
                ldm_x4(sAl + ar, fAl[mi]);
            }
#pragma unroll
            for (int ni = 0; ni < NT; ni++) {
                const uint32_t br = (wn0 + ni * 8 + (lane & 7)) * LDSB + bcol;
                ldm_x2(sBh + br, fBh[ni]);
                ldm_x2(sBl + br, fBl[ni]);
            }
#pragma unroll
            for (int mi = 0; mi < MT; mi++)
#pragma unroll
                for (int ni = 0; ni < NT; ni++) {
                    mma16816(acc[mi][ni], fAh[mi], fBh[ni]);
                    mma16816(acc[mi][ni], fAh[mi], fBl[ni]);
                    mma16816(acc[mi][ni], fAl[mi], fBh[ni]);
                }
        }
        __syncthreads();
    }

    const int qr = lane >> 2;
    const int qc = (lane & 3) * 2;
#pragma unroll
    for (int mi = 0; mi < MT; mi++)
#pragma unroll
        for (int ni = 0; ni < NT; ni++)
#pragma unroll
            for (int h2 = 0; h2 < 2; h2++) {
                const int row = m0 + wm0 + mi * 16 + qr + h2 * 8;
                const int col = n0 + wn0 + ni * 8 + qc;
                float v0 = acc[mi][ni][h2 * 2 + 0] * scale;
                float v1 = acc[mi][ni][h2 * 2 + 1] * scale;
                if (bias) { v0 += bias[col]; v1 += bias[col + 1]; }
                if (mode == 0) {
                    float2 fv = make_float2(v0, v1);
                    *(float2*)&Cf[(size_t)z * sC + (size_t)row * ldc + col] = fv;
                } else if (mode == 1) {
                    const int b = row >> 11, s = row & 2047, h = col >> 6, dk = col & 63;
                    const size_t o = ((((size_t)b * HH + h) * SS) + s) * DK + dk;
                    __nv_bfloat16 h0, l0, h1, l1;
                    split2(v0, h0, l0); split2(v1, h1, l1);
                    *(__nv_bfloat162*)&Ch[o] = __nv_bfloat162(h0, h1);
                    *(__nv_bfloat162*)&Cl[o] = __nv_bfloat162(l0, l1);
                } else {   // mode 2
                    const int b = row >> 11, s = row & 2047, h = col >> 6, dk = col & 63;
                    const size_t o = ((((size_t)b * HH + h) * DK) + dk) * SS + s;
                    __nv_bfloat16 h0, l0, h1, l1;
                    split2(v0, h0, l0); split2(v1, h1, l1);
                    Ch[o] = h0; Cl[o] = l0;
                    Ch[o + SS] = h1; Cl[o + SS] = l1;
                }
            }
}

// ─────────────────────────────────────────────────────────────────────────────
// Fused flash attention: per (q-tile 128, bh) block.
//   S = (Q K^T)/8  (3-pass hi/lo mma, fp32 acc in regs)
//   online softmax (running max/sum), P split hi/lo in registers
//   O += P V      (3-pass hi/lo mma)
// K tiles of 64 rows, double-buffered cp.async. P never touches DRAM.
// Output: merged-head bf16 hi/lo (g_Oh/g_Ol).
// ─────────────────────────────────────────────────────────────────────────────
#define BKV    64
#define LDK    144                       // 64 bf16 = 128B row + 16B pad
#define KPLANE (64 * LDK)                // 9216
#define QPLANE (128 * LDK)               // 18432
#define OFF_Q  0
#define OFF_S  (2 * QPLANE)              // 36864
#define STAGEA (4 * KPLANE)              // Kh,Kl,Vh,Vl = 36864
#define FA_SMEM (OFF_S + 2 * STAGEA)     // 110592

__global__ void __launch_bounds__(256, 1) fused_attn()
{
    extern __shared__ __align__(16) char smem[];
    const uint32_t sb = smem_u32(smem);

    const int tid  = threadIdx.x;
    const int w    = tid >> 5;
    const int lane = tid & 31;
    const int qbase = blockIdx.x * 128;      // q-tile start within head
    const int bh   = blockIdx.y;
    const int b    = bh / HH, h = bh % HH;

    const __nv_bfloat16* pQh = g_Qh  + (size_t)bh * SS * DK;
    const __nv_bfloat16* pQl = g_Ql  + (size_t)bh * SS * DK;
    const __nv_bfloat16* pKh = g_Kh  + (size_t)bh * SS * DK;
    const __nv_bfloat16* pKl = g_Kl  + (size_t)bh * SS * DK;
    const __nv_bfloat16* pVh = g_Vth + (size_t)bh * DK * SS;
    const __nv_bfloat16* pVl = g_Vtl + (size_t)bh * DK * SS;

    // ---- loaders ----
    auto load_q = [&]() {
        for (int c = tid; c < 1024; c += 256) {          // 128 rows x 8 chunks
            const int r = c >> 3, kc = c & 7;
            const size_t go = (size_t)(qbase + r) * DK + kc * 8;
            cp_async16(sb + OFF_Q + r * LDK + kc * 16,          pQh + go);
            cp_async16(sb + OFF_Q + QPLANE + r * LDK + kc * 16, pQl + go);
        }
        cp_commit();
    };
    auto load_kv = [&](int st, int j0) {
        const uint32_t s0 = sb + OFF_S + st * STAGEA;
        for (int c = tid; c < 512; c += 256) {           // 64 rows x 8 chunks
            const int r = c >> 3, kc = c & 7;
            const size_t gk = (size_t)(j0 + r) * DK + kc * 8;
            cp_async16(s0 + r * LDK + kc * 16,              pKh + gk);
            cp_async16(s0 + KPLANE + r * LDK + kc * 16,     pKl + gk);
            const size_t gv = (size_t)r * SS + j0 + kc * 8; // V^T row r = dk
            cp_async16(s0 + 2 * KPLANE + r * LDK + kc * 16, pVh + gv);
            cp_async16(s0 + 3 * KPLANE + r * LDK + kc * 16, pVl + gv);
        }
        cp_commit();
    };

    load_q();
    load_kv(0, 0);

    uint32_t Qhf[4][4], Qlf[4][4];
    float Oa[8][4];
#pragma unroll
    for (int ni = 0; ni < 8; ni++)
#pragma unroll
        for (int q = 0; q < 4; q++) Oa[ni][q] = 0.f;
    float m0 = -1e30f, m1 = -1e30f, l0 = 0.f, l1 = 0.f;

    constexpr int NSTEP = SS / BKV;   // 32
    for (int jt = 0; jt < NSTEP; jt++) {
        if (jt + 1 < NSTEP) { load_kv((jt + 1) & 1, (jt + 1) * BKV); cp_wait_1(); }
        else                { cp_wait_all(); }
        __syncthreads();

        if (jt == 0) {
            // Q fragments once (A operand: m16k16)
#pragma unroll
            for (int ks = 0; ks < 4; ks++) {
                const uint32_t ar = (uint32_t)(w * 16 + (lane & 15)) * LDK +
                                    ks * 32 + (lane >> 4) * 16;
                ldm_x4(sb + OFF_Q + ar, Qhf[ks]);
                ldm_x4(sb + OFF_Q + QPLANE + ar, Qlf[ks]);
            }
        }

        const uint32_t sK = sb + OFF_S + (jt & 1) * STAGEA;
        const uint32_t sV = sK + 2 * KPLANE;

        // ---- S = Q K^T (3-pass) ----
        float Sa[8][4];
#pragma unroll
        for (int ni = 0; ni < 8; ni++)
#pragma unroll
            for (int q = 0; q < 4; q++) Sa[ni][q] = 0.f;

#pragma unroll
        for (int ks = 0; ks < 4; ks++) {
            uint32_t kh[8][2], kl[8][2];
#pragma unroll
            for (int ni = 0; ni < 8; ni++) {
                const uint32_t br = (uint32_t)(ni * 8 + (lane & 7)) * LDK +
                                    ks * 32 + ((lane >> 3) & 1) * 16;
                ldm_x2(sK + br, kh[ni]);
                ldm_x2(sK + KPLANE + br, kl[ni]);
            }
#pragma unroll
            for (int ni = 0; ni < 8; ni++) {
                mma16816(Sa[ni], Qhf[ks], kh[ni]);
                mma16816(Sa[ni], Qhf[ks], kl[ni]);
                mma16816(Sa[ni], Qlf[ks], kh[ni]);
            }
        }

        // ---- online softmax ----
        float mx0 = -1e30f, mx1 = -1e30f;
#pragma unroll
        for (int ni = 0; ni < 8; ni++) {
            Sa[ni][0] *= 0.125f; Sa[ni][1] *= 0.125f;
            Sa[ni][2] *= 0.125f; Sa[ni][3] *= 0.125f;
            mx0 = fmaxf(mx0, fmaxf(Sa[ni][0], Sa[ni][1]));
            mx1 = fmaxf(mx1, fmaxf(Sa[ni][2], Sa[ni][3]));
        }
        mx0 = fmaxf(mx0, __shfl_xor_sync(0xffffffffu, mx0, 1));
        mx0 = fmaxf(mx0, __shfl_xor_sync(0xffffffffu, mx0, 2));
        mx1 = fmaxf(mx1, __shfl_xor_sync(0xffffffffu, mx1, 1));
        mx1 = fmaxf(mx1, __shfl_xor_sync(0xffffffffu, mx1, 2));

        const float mn0 = fmaxf(m0, mx0), mn1 = fmaxf(m1, mx1);
        const float a0 = __expf(m0 - mn0), a1 = __expf(m1 - mn1);
        m0 = mn0; m1 = mn1;

        float rs0 = 0.f, rs1 = 0.f;
#pragma unroll
        for (int ni = 0; ni < 8; ni++) {
            Sa[ni][0] = __expf(Sa[ni][0] - mn0);
            Sa[ni][1] = __expf(Sa[ni][1] - mn0);
            Sa[ni][2] = __expf(Sa[ni][2] - mn1);
            Sa[ni][3] = __expf(Sa[ni][3] - mn1);
            rs0 += Sa[ni][0] + Sa[ni][1];
            rs1 += Sa[ni][2] + Sa[ni][3];
            Oa[ni][0] *= a0; Oa[ni][1] *= a0;
            Oa[ni][2] *= a1; Oa[ni][3] *= a1;
        }
        rs0 += __shfl_xor_sync(0xffffffffu, rs0, 1);
        rs0 += __shfl_xor_sync(0xffffffffu, rs0, 2);
        rs1 += __shfl_xor_sync(0xffffffffu, rs1, 1);
        rs1 += __shfl_xor_sync(0xffffffffu, rs1, 2);
        l0 = l0 * a0 + rs0;
        l1 = l1 * a1 + rs1;

        // ---- P -> bf16 hi/lo A-fragments (register remap, no smem) ----
        uint32_t ph[4][4], pl[4][4];
#pragma unroll
        for (int t = 0; t < 4; t++) {
            __nv_bfloat16 h00, l00, h01, l01, h02, l02, h03, l03;
            __nv_bfloat16 h10, l10, h11, l11, h12, l12, h13, l13;
            split2(Sa[2*t][0], h00, l00);   split2(Sa[2*t][1], h01, l01);
            split2(Sa[2*t][2], h02, l02);   split2(Sa[2*t][3], h03, l03);
            split2(Sa[2*t+1][0], h10, l10); split2(Sa[2*t+1][1], h11, l11);
            split2(Sa[2*t+1][2], h12, l12); split2(Sa[2*t+1][3], h13, l13);
            ph[t][0] = pack_bf2(h00, h01);  pl[t][0] = pack_bf2(l00, l01);
            ph[t][1] = pack_bf2(h02, h03);  pl[t][1] = pack_bf2(l02, l03);
            ph[t][2] = pack_bf2(h10, h11);  pl[t][2] = pack_bf2(l10, l11);
            ph[t][3] = pack_bf2(h12, h13);  pl[t][3] = pack_bf2(l12, l13);
        }

        // ---- O += P V (3-pass) ----
#pragma unroll
        for (int t = 0; t < 4; t++) {
            uint32_t vh[8][2], vl[8][2];
#pragma unroll
            for (int ni = 0; ni < 8; ni++) {
                const uint32_t br = (uint32_t)(ni * 8 + (lane & 7)) * LDK +
                                    t * 32 + ((lane >> 3) & 1) * 16;
                ldm_x2(sV + br, vh[ni]);
                ldm_x2(sV + KPLANE + br, vl[ni]);
            }
#pragma unroll
            for (int ni = 0; ni < 8; ni++) {
                mma16816(Oa[ni], ph[t], vh[ni]);
                mma16816(Oa[ni], ph[t], vl[ni]);
                mma16816(Oa[ni], pl[t], vh[ni]);
            }
        }
        __syncthreads();
    }

    // ---- epilogue: O /= l, write merged-head bf16 hi/lo ----
    const float inv0 = 1.f / l0, inv1 = 1.f / l1;
    const int qr = lane >> 2, qc = (lane & 3) * 2;
    const int s0r = qbase + w * 16 + qr;
#pragma unroll
    for (int ni = 0; ni < 8; ni++) {
        const int col = ni * 8 + qc;
        const size_t o0 = ((size_t)(b * SS + s0r))     * DD + h * DK + col;
        const size_t o1 = ((size_t)(b * SS + s0r + 8)) * DD + h * DK + col;
        __nv_bfloat16 h0, lo0, h1, lo1;
        split2(Oa[ni][0] * inv0, h0, lo0);
        split2(Oa[ni][1] * inv0, h1, lo1);
        *(__nv_bfloat162*)&g_Oh[o0] = __nv_bfloat162(h0, h1);
        *(__nv_bfloat162*)&g_Ol[o0] = __nv_bfloat162(lo0, lo1);
        split2(Oa[ni][2] * inv1, h0, lo0);
        split2(Oa[ni][3] * inv1, h1, lo1);
        *(__nv_bfloat162*)&g_Oh[o1] = __nv_bfloat162(h0, h1);
        *(__nv_bfloat162*)&g_Ol[o1] = __nv_bfloat162(lo0, lo1);
    }
}

// ─────────────────────────────────────────────────────────────────────────────
// Elementwise fp32 -> bf16 hi/lo split
// ─────────────────────────────────────────────────────────────────────────────
__global__ void __launch_bounds__(256) split_f32(
    const float* __restrict__ s, __nv_bfloat16* __restrict__ h,
    __nv_bfloat16* __restrict__ l, int n)
{
    int i = blockIdx.x * 256 + threadIdx.x;
    if (i < n) {
        float x = s[i];
        __nv_bfloat16 hi, lo; split2(x, hi, lo);
        h[i] = hi; l[i] = lo;
    }
}

// ─────────────────────────────────────────────────────────────────────────────
// kernel_launch
// Input order: k, q, v, mask, wq, bq, wk, bk, wv, bv, wo, bo
// ─────────────────────────────────────────────────────────────────────────────
extern "C" void kernel_launch(void* const* d_in, const int* in_sizes, int n_in,
                              void* d_out, int out_size)
{
    const float* k_in = (const float*)d_in[0];
    const float* q_in = (const float*)d_in[1];
    const float* v_in = (const float*)d_in[2];
    const float* wq = (const float*)d_in[4];
    const float* bq = (const float*)d_in[5];
    const float* wk = (const float*)d_in[6];
    const float* bk = (const float*)d_in[7];
    const float* wv = (const float*)d_in[8];
    const float* bv = (const float*)d_in[9];
    const float* wo = (const float*)d_in[10];
    const float* bo = (const float*)d_in[11];
    float* out = (float*)d_out;

    __nv_bfloat16 *xqh, *xql, *xkh, *xkl, *xvh, *xvl;
    __nv_bfloat16 *wqh, *wql, *wkh, *wkl, *wvh, *wvl, *woh, *wol;
    __nv_bfloat16 *Qh, *Ql, *Kh, *Kl, *Vth, *Vtl, *Oh, *Ol;
    cudaGetSymbolAddress((void**)&xqh, g_xqh); cudaGetSymbolAddress((void**)&xql, g_xql);
    cudaGetSymbolAddress((void**)&xkh, g_xkh); cudaGetSymbolAddress((void**)&xkl, g_xkl);
    cudaGetSymbolAddress((void**)&xvh, g_xvh); cudaGetSymbolAddress((void**)&xvl, g_xvl);
    cudaGetSymbolAddress((void**)&wqh, g_wqh); cudaGetSymbolAddress((void**)&wql, g_wql);
    cudaGetSymbolAddress((void**)&wkh, g_wkh); cudaGetSymbolAddress((void**)&wkl, g_wkl);
    cudaGetSymbolAddress((void**)&wvh, g_wvh); cudaGetSymbolAddress((void**)&wvl, g_wvl);
    cudaGetSymbolAddress((void**)&woh, g_woh); cudaGetSymbolAddress((void**)&wol, g_wol);
    cudaGetSymbolAddress((void**)&Qh,  g_Qh);  cudaGetSymbolAddress((void**)&Ql,  g_Ql);
    cudaGetSymbolAddress((void**)&Kh,  g_Kh);  cudaGetSymbolAddress((void**)&Kl,  g_Kl);
    cudaGetSymbolAddress((void**)&Vth, g_Vth); cudaGetSymbolAddress((void**)&Vtl, g_Vtl);
    cudaGetSymbolAddress((void**)&Oh,  g_Oh);  cudaGetSymbolAddress((void**)&Ol,  g_Ol);

    cudaFuncSetAttribute(wgemm<128>, cudaFuncAttributeMaxDynamicSharedMemorySize, 81920);
    cudaFuncSetAttribute(fused_attn, cudaFuncAttributeMaxDynamicSharedMemorySize, FA_SMEM);

    const int nAct = MM * DD, nW = DD * DD;

    // 1. fp32 -> bf16 hi/lo splits
    split_f32<<<(nAct + 255) / 256, 256>>>(q_in, xqh, xql, nAct);
    split_f32<<<(nAct + 255) / 256, 256>>>(k_in, xkh, xkl, nAct);
    split_f32<<<(nAct + 255) / 256, 256>>>(v_in, xvh, xvl, nAct);
    split_f32<<<(nW + 255) / 256, 256>>>(wq, wqh, wql, nW);
    split_f32<<<(nW + 255) / 256, 256>>>(wk, wkh, wkl, nW);
    split_f32<<<(nW + 255) / 256, 256>>>(wv, wvh, wvl, nW);
    split_f32<<<(nW + 255) / 256, 256>>>(wo, woh, wol, nW);

    // 2. Projections (M=4096, N=768, K=768)
    dim3 gproj(MM / 128, DD / 128, 1);
    wgemm<128><<<gproj, 256, 81920>>>(xqh, xql, DD, 0, wqh, wql, DD, 0,
                                      DD, 1.f, bq, 1, nullptr, Qh, Ql, 0, 0);
    wgemm<128><<<gproj, 256, 81920>>>(xkh, xkl, DD, 0, wkh, wkl, DD, 0,
                                      DD, 1.f, bk, 1, nullptr, Kh, Kl, 0, 0);
    wgemm<128><<<gproj, 256, 81920>>>(xvh, xvl, DD, 0, wvh, wvl, DD, 0,
                                      DD, 1.f, bv, 2, nullptr, Vth, Vtl, 0, 0);

    // 3. Fused attention (scores + softmax + PV)
    fused_attn<<<dim3(SS / 128, BH), 256, FA_SMEM>>>();

    // 4. Output projection into d_out (M=4096, N=768, K=768)
    wgemm<128><<<gproj, 256, 81920>>>(Oh, Ol, DD, 0, woh, wol, DD, 0,
                                      DD, 1.f, bo, 0, out, nullptr, nullptr, DD, 0);
}

// round 5
// speedup vs baseline: 5.9847x; 2.1860x over previous
#include <cuda_runtime.h>
#include <cuda_fp16.h>
#include <cstdint>

// ─────────────────────────────────────────────────────────────────────────────
// Dims
// ─────────────────────────────────────────────────────────────────────────────
#define BB 2
#define SS 2048
#define DD 768
#define HH 12
#define DK 64
#define BH 24           // BB*HH
#define MM 4096         // BB*SS

// ─────────────────────────────────────────────────────────────────────────────
// Scratch (static device globals — no allocation). Single fp16 plane each.
// ─────────────────────────────────────────────────────────────────────────────
__device__ __half g_xq[MM * DD], g_xk[MM * DD], g_xv[MM * DD];
__device__ __half g_wq[DD * DD], g_wk[DD * DD], g_wv[DD * DD], g_wo[DD * DD];
__device__ __half g_Q[BH * SS * DK];
__device__ __half g_K[BH * SS * DK];
__device__ __half g_Vt[BH * SS * DK];    // [bh, dk, s]
__device__ __half g_O[MM * DD];          // merged heads [B*S, D]

// ─────────────────────────────────────────────────────────────────────────────
// PTX helpers (baseline ISA only — harness targets sm_103 non-'a', no tcgen05)
// ─────────────────────────────────────────────────────────────────────────────
__device__ __forceinline__ uint32_t smem_u32(const void* p) {
    uint32_t a;
    asm("{ .reg .u64 t; cvta.to.shared.u64 t, %1; cvt.u32.u64 %0, t; }"
        : "=r"(a) : "l"(p));
    return a;
}

__device__ __forceinline__ void cp_async16(uint32_t saddr, const void* gaddr) {
    asm volatile("cp.async.ca.shared.global [%0], [%1], 16;"
                 :: "r"(saddr), "l"(gaddr));
}
__device__ __forceinline__ void cp_commit() {
    asm volatile("cp.async.commit_group;");
}
__device__ __forceinline__ void cp_wait_all() {
    asm volatile("cp.async.wait_group 0;");
}
__device__ __forceinline__ void cp_wait_1() {
    asm volatile("cp.async.wait_group 1;");
}

__device__ __forceinline__ void ldm_x4(uint32_t addr, uint32_t* r) {
    asm volatile("ldmatrix.sync.aligned.m8n8.x4.shared.b16 {%0,%1,%2,%3}, [%4];"
                 : "=r"(r[0]), "=r"(r[1]), "=r"(r[2]), "=r"(r[3]) : "r"(addr));
}
__device__ __forceinline__ void ldm_x2(uint32_t addr, uint32_t* r) {
    asm volatile("ldmatrix.sync.aligned.m8n8.x2.shared.b16 {%0,%1}, [%2];"
                 : "=r"(r[0]), "=r"(r[1]) : "r"(addr));
}

// fp16 in, fp32 accumulate
__device__ __forceinline__ void mma16816(float* c, const uint32_t* a, const uint32_t* b) {
    asm volatile(
        "mma.sync.aligned.m16n8k16.row.col.f32.f16.f16.f32 "
        "{%0,%1,%2,%3}, {%4,%5,%6,%7}, {%8,%9}, {%0,%1,%2,%3};"
        : "+f"(c[0]), "+f"(c[1]), "+f"(c[2]), "+f"(c[3])
        : "r"(a[0]), "r"(a[1]), "r"(a[2]), "r"(a[3]), "r"(b[0]), "r"(b[1]));
}

__device__ __forceinline__ uint32_t pack_h2(float a, float b) {
    __half2 t = __floats2half2_rn(a, b);   // a in low half
    return *(uint32_t*)&t;
}

// ─────────────────────────────────────────────────────────────────────────────
// Warp-MMA GEMM (NT): C[m,n] = scale * sum_k A[m,k]*B[n,k] (+bias), fp16 ops.
// BM=128, BK=32, 256 threads, 2-stage cp.async. 80B smem row stride.
// mode 0: fp32 -> Cf[row*ldc + col]
// mode 1: fp16 head-split      -> Ch[((b*H+h)*SS+s)*DK+dk]
// mode 2: fp16 head-split+T    -> Ch[((b*H+h)*DK+dk)*SS+s]
// ─────────────────────────────────────────────────────────────────────────────
template <int BN>
__global__ void __launch_bounds__(256) wgemm(
    const __half* __restrict__ A, int lda,
    const __half* __restrict__ B, int ldb,
    int K, float scale, const float* __restrict__ bias, int mode,
    float* __restrict__ Cf, __half* __restrict__ Ch, int ldc)
{
    constexpr int BM = 128;
    constexpr int WARPS_M = 2;
    constexpr int WM = BM / WARPS_M;       // 64
    constexpr int WN = BN / 4;             // 32
    constexpr int MT = WM / 16;            // 4
    constexpr int NT = WN / 8;             // 4

    constexpr int LDSB  = 80;              // 32 fp16 = 64B + 16B pad
    constexpr int ATILE = BM * LDSB;       // 10240
    constexpr int BTILE = BN * LDSB;
    constexpr int STAGE = ATILE + BTILE;

    extern __shared__ __align__(16) char smem[];
    const uint32_t sb = smem_u32(smem);

    const int tid  = threadIdx.x;
    const int w    = tid >> 5;
    const int lane = tid & 31;
    const int m0   = blockIdx.x * BM;
    const int n0   = blockIdx.y * BN;

    const int wm0 = (w % WARPS_M) * WM;
    const int wn0 = (w / WARPS_M) * WN;

    const __half* pA = A + (size_t)m0 * lda;
    const __half* pB = B + (size_t)n0 * ldb;

    auto load_stage = [&](int st, int k0) {
        const uint32_t s0 = sb + st * STAGE;
        for (int c = tid; c < BM * 4; c += 256) {
            const int r = c >> 2, kc = c & 3;
            cp_async16(s0 + r * LDSB + kc * 16, pA + (size_t)r * lda + k0 + kc * 8);
        }
        for (int c = tid; c < BN * 4; c += 256) {
            const int r = c >> 2, kc = c & 3;
            cp_async16(s0 + ATILE + r * LDSB + kc * 16, pB + (size_t)r * ldb + k0 + kc * 8);
        }
        cp_commit();
    };

    float acc[MT][NT][4];
#pragma unroll
    for (int i = 0; i < MT; i++)
#pragma unroll
        for (int j = 0; j < NT; j++)
#pragma unroll
            for (int q = 0; q < 4; q++) acc[i][j][q] = 0.f;

    const int niter = K >> 5;
    load_stage(0, 0);

    for (int it = 0; it < niter; it++) {
        cp_wait_all();
        __syncthreads();
        if (it + 1 < niter) load_stage((it + 1) & 1, (it + 1) << 5);

        const uint32_t sA = sb + (it & 1) * STAGE;
        const uint32_t sB = sA + ATILE;

#pragma unroll
        for (int ks = 0; ks < 2; ks++) {
            uint32_t fA[MT][4], fB[NT][2];
            const uint32_t acol = ks * 32 + (lane >> 4) * 16;
            const uint32_t bcol = ks * 32 + ((lane >> 3) & 1) * 16;
#pragma unroll
            for (int mi = 0; mi < MT; mi++)
                ldm_x4(sA + (wm0 + mi * 16 + (lane & 15)) * LDSB + acol, fA[mi]);
#pragma unroll
            for (int ni = 0; ni < NT; ni++)
                ldm_x2(sB + (wn0 + ni * 8 + (lane & 7)) * LDSB + bcol, fB[ni]);
#pragma unroll
            for (int mi = 0; mi < MT; mi++)
#pragma unroll
                for (int ni = 0; ni < NT; ni++)
                    mma16816(acc[mi][ni], fA[mi], fB[ni]);
        }
        __syncthreads();
    }

    const int qr = lane >> 2;
    const int qc = (lane & 3) * 2;
#pragma unroll
    for (int mi = 0; mi < MT; mi++)
#pragma unroll
        for (int ni = 0; ni < NT; ni++)
#pragma unroll
            for (int h2 = 0; h2 < 2; h2++) {
                const int row = m0 + wm0 + mi * 16 + qr + h2 * 8;
                const int col = n0 + wn0 + ni * 8 + qc;
                float v0 = acc[mi][ni][h2 * 2 + 0] * scale;
                float v1 = acc[mi][ni][h2 * 2 + 1] * scale;
                if (bias) { v0 += bias[col]; v1 += bias[col + 1]; }
                if (mode == 0) {
                    *(float2*)&Cf[(size_t)row * ldc + col] = make_float2(v0, v1);
                } else if (mode == 1) {
                    const int b = row >> 11, s = row & 2047, h = col >> 6, dk = col & 63;
                    const size_t o = ((((size_t)b * HH + h) * SS) + s) * DK + dk;
                    *(__half2*)&Ch[o] = __floats2half2_rn(v0, v1);
                } else {   // mode 2 (transposed head-split)
                    const int b = row >> 11, s = row & 2047, h = col >> 6, dk = col & 63;
                    const size_t o = ((((size_t)b * HH + h) * DK) + dk) * SS + s;
                    Ch[o]      = __float2half_rn(v0);
                    Ch[o + SS] = __float2half_rn(v1);
                }
            }
}

// ─────────────────────────────────────────────────────────────────────────────
// Fused flash attention: per (q-tile 128, bh) block. fp16 single-pass MMA.
// ─────────────────────────────────────────────────────────────────────────────
#define BKV    64
#define LDK    144                       // 64 fp16 = 128B row + 16B pad
#define KPLANE (64 * LDK)                // 9216
#define QPLANE (128 * LDK)               // 18432
#define OFF_Q  0
#define OFF_S  QPLANE                    // 18432
#define STAGEA (2 * KPLANE)              // K + V = 18432
#define FA_SMEM (OFF_S + 2 * STAGEA)     // 55296

__global__ void __launch_bounds__(256) fused_attn()
{
    extern __shared__ __align__(16) char smem[];
    const uint32_t sb = smem_u32(smem);

    const int tid  = threadIdx.x;
    const int w    = tid >> 5;
    const int lane = tid & 31;
    const int qbase = blockIdx.x * 128;
    const int bh   = blockIdx.y;
    const int b    = bh / HH, h = bh % HH;

    const __half* pQ = g_Q  + (size_t)bh * SS * DK;
    const __half* pK = g_K  + (size_t)bh * SS * DK;
    const __half* pV = g_Vt + (size_t)bh * DK * SS;

    auto load_q = [&]() {
        for (int c = tid; c < 1024; c += 256) {          // 128 rows x 8 chunks
            const int r = c >> 3, kc = c & 7;
            cp_async16(sb + OFF_Q + r * LDK + kc * 16,
                       pQ + (size_t)(qbase + r) * DK + kc * 8);
        }
        cp_commit();
    };
    auto load_kv = [&](int st, int j0) {
        const uint32_t s0 = sb + OFF_S + st * STAGEA;
        for (int c = tid; c < 512; c += 256) {           // 64 rows x 8 chunks
            const int r = c >> 3, kc = c & 7;
            cp_async16(s0 + r * LDK + kc * 16,
                       pK + (size_t)(j0 + r) * DK + kc * 8);
            cp_async16(s0 + KPLANE + r * LDK + kc * 16,
                       pV + (size_t)r * SS + j0 + kc * 8);   // V^T row r = dk
        }
        cp_commit();
    };

    load_q();
    load_kv(0, 0);

    uint32_t Qf[4][4];
    float Oa[8][4];
#pragma unroll
    for (int ni = 0; ni < 8; ni++)
#pragma unroll
        for (int q = 0; q < 4; q++) Oa[ni][q] = 0.f;
    float m0 = -1e30f, m1 = -1e30f, l0 = 0.f, l1 = 0.f;

    constexpr int NSTEP = SS / BKV;   // 32
    for (int jt = 0; jt < NSTEP; jt++) {
        if (jt + 1 < NSTEP) { load_kv((jt + 1) & 1, (jt + 1) * BKV); cp_wait_1(); }
        else                { cp_wait_all(); }
        __syncthreads();

        if (jt == 0) {
#pragma unroll
            for (int ks = 0; ks < 4; ks++) {
                const uint32_t ar = (uint32_t)(w * 16 + (lane & 15)) * LDK +
                                    ks * 32 + (lane >> 4) * 16;
                ldm_x4(sb + OFF_Q + ar, Qf[ks]);
            }
        }

        const uint32_t sK = sb + OFF_S + (jt & 1) * STAGEA;
        const uint32_t sV = sK + KPLANE;

        // ---- S = Q K^T ----
        float Sa[8][4];
#pragma unroll
        for (int ni = 0; ni < 8; ni++)
#pragma unroll
            for (int q = 0; q < 4; q++) Sa[ni][q] = 0.f;

#pragma unroll
        for (int ks = 0; ks < 4; ks++) {
            uint32_t kf[8][2];
#pragma unroll
            for (int ni = 0; ni < 8; ni++)
                ldm_x2(sK + (uint32_t)(ni * 8 + (lane & 7)) * LDK +
                       ks * 32 + ((lane >> 3) & 1) * 16, kf[ni]);
#pragma unroll
            for (int ni = 0; ni < 8; ni++)
                mma16816(Sa[ni], Qf[ks], kf[ni]);
        }

        // ---- online softmax ----
        float mx0 = -1e30f, mx1 = -1e30f;
#pragma unroll
        for (int ni = 0; ni < 8; ni++) {
            Sa[ni][0] *= 0.125f; Sa[ni][1] *= 0.125f;
            Sa[ni][2] *= 0.125f; Sa[ni][3] *= 0.125f;
            mx0 = fmaxf(mx0, fmaxf(Sa[ni][0], Sa[ni][1]));
            mx1 = fmaxf(mx1, fmaxf(Sa[ni][2], Sa[ni][3]));
        }
        mx0 = fmaxf(mx0, __shfl_xor_sync(0xffffffffu, mx0, 1));
        mx0 = fmaxf(mx0, __shfl_xor_sync(0xffffffffu, mx0, 2));
        mx1 = fmaxf(mx1, __shfl_xor_sync(0xffffffffu, mx1, 1));
        mx1 = fmaxf(mx1, __shfl_xor_sync(0xffffffffu, mx1, 2));

        const float mn0 = fmaxf(m0, mx0), mn1 = fmaxf(m1, mx1);
        const float a0 = __expf(m0 - mn0), a1 = __expf(m1 - mn1);
        m0 = mn0; m1 = mn1;

        float rs0 = 0.f, rs1 = 0.f;
#pragma unroll
        for (int ni = 0; ni < 8; ni++) {
            Sa[ni][0] = __expf(Sa[ni][0] - mn0);
            Sa[ni][1] = __expf(Sa[ni][1] - mn0);
            Sa[ni][2] = __expf(Sa[ni][2] - mn1);
            Sa[ni][3] = __expf(Sa[ni][3] - mn1);
            rs0 += Sa[ni][0] + Sa[ni][1];
            rs1 += Sa[ni][2] + Sa[ni][3];
            Oa[ni][0] *= a0; Oa[ni][1] *= a0;
            Oa[ni][2] *= a1; Oa[ni][3] *= a1;
        }
        rs0 += __shfl_xor_sync(0xffffffffu, rs0, 1);
        rs0 += __shfl_xor_sync(0xffffffffu, rs0, 2);
        rs1 += __shfl_xor_sync(0xffffffffu, rs1, 1);
        rs1 += __shfl_xor_sync(0xffffffffu, rs1, 2);
        l0 = l0 * a0 + rs0;
        l1 = l1 * a1 + rs1;

        // ---- P -> fp16 A-fragments (register remap, no smem) ----
        uint32_t pf[4][4];
#pragma unroll
        for (int t = 0; t < 4; t++) {
            pf[t][0] = pack_h2(Sa[2*t][0],   Sa[2*t][1]);
            pf[t][1] = pack_h2(Sa[2*t][2],   Sa[2*t][3]);
            pf[t][2] = pack_h2(Sa[2*t+1][0], Sa[2*t+1][1]);
            pf[t][3] = pack_h2(Sa[2*t+1][2], Sa[2*t+1][3]);
        }

        // ---- O += P V ----
#pragma unroll
        for (int t = 0; t < 4; t++) {
            uint32_t vf[8][2];
#pragma unroll
            for (int ni = 0; ni < 8; ni++)
                ldm_x2(sV + (uint32_t)(ni * 8 + (lane & 7)) * LDK +
                       t * 32 + ((lane >> 3) & 1) * 16, vf[ni]);
#pragma unroll
            for (int ni = 0; ni < 8; ni++)
                mma16816(Oa[ni], pf[t], vf[ni]);
        }
        __syncthreads();
    }

    // ---- epilogue: O /= l, write merged-head fp16 ----
    const float inv0 = 1.f / l0, inv1 = 1.f / l1;
    const int qr = lane >> 2, qc = (lane & 3) * 2;
    const int s0r = qbase + w * 16 + qr;
#pragma unroll
    for (int ni = 0; ni < 8; ni++) {
        const int col = ni * 8 + qc;
        const size_t o0 = ((size_t)(b * SS + s0r))     * DD + h * DK + col;
        const size_t o1 = ((size_t)(b * SS + s0r + 8)) * DD + h * DK + col;
        *(__half2*)&g_O[o0] = __floats2half2_rn(Oa[ni][0] * inv0, Oa[ni][1] * inv0);
        *(__half2*)&g_O[o1] = __floats2half2_rn(Oa[ni][2] * inv1, Oa[ni][3] * inv1);
    }
}

// ─────────────────────────────────────────────────────────────────────────────
// fp32 -> fp16 convert (vectorized x4)
// ─────────────────────────────────────────────────────────────────────────────
__global__ void __launch_bounds__(256) cvt16(
    const float4* __restrict__ s, __half* __restrict__ d, int n4)
{
    int i = blockIdx.x * 256 + threadIdx.x;
    if (i < n4) {
        float4 v = s[i];
        __half2 a = __floats2half2_rn(v.x, v.y);
        __half2 b = __floats2half2_rn(v.z, v.w);
        *(uint2*)(d + 4 * (size_t)i) = make_uint2(*(uint32_t*)&a, *(uint32_t*)&b);
    }
}

// ─────────────────────────────────────────────────────────────────────────────
// kernel_launch
// Input order: k, q, v, mask, wq, bq, wk, bk, wv, bv, wo, bo
// ─────────────────────────────────────────────────────────────────────────────
extern "C" void kernel_launch(void* const* d_in, const int* in_sizes, int n_in,
                              void* d_out, int out_size)
{
    const float* k_in = (const float*)d_in[0];
    const float* q_in = (const float*)d_in[1];
    const float* v_in = (const float*)d_in[2];
    const float* wq = (const float*)d_in[4];
    const float* bq = (const float*)d_in[5];
    const float* wk = (const float*)d_in[6];
    const float* bk = (const float*)d_in[7];
    const float* wv = (const float*)d_in[8];
    const float* bv = (const float*)d_in[9];
    const float* wo = (const float*)d_in[10];
    const float* bo = (const float*)d_in[11];
    float* out = (float*)d_out;

    __half *xq, *xk, *xv, *w_q, *w_k, *w_v, *w_o, *Q, *K, *Vt, *O;
    cudaGetSymbolAddress((void**)&xq, g_xq);
    cudaGetSymbolAddress((void**)&xk, g_xk);
    cudaGetSymbolAddress((void**)&xv, g_xv);
    cudaGetSymbolAddress((void**)&w_q, g_wq);
    cudaGetSymbolAddress((void**)&w_k, g_wk);
    cudaGetSymbolAddress((void**)&w_v, g_wv);
    cudaGetSymbolAddress((void**)&w_o, g_wo);
    cudaGetSymbolAddress((void**)&Q,  g_Q);
    cudaGetSymbolAddress((void**)&K,  g_K);
    cudaGetSymbolAddress((void**)&Vt, g_Vt);
    cudaGetSymbolAddress((void**)&O,  g_O);

    cudaFuncSetAttribute(fused_attn, cudaFuncAttributeMaxDynamicSharedMemorySize, FA_SMEM);

    const int nAct4 = MM * DD / 4, nW4 = DD * DD / 4;

    // 1. fp32 -> fp16 conversions
    cvt16<<<(nAct4 + 255) / 256, 256>>>((const float4*)q_in, xq, nAct4);
    cvt16<<<(nAct4 + 255) / 256, 256>>>((const float4*)k_in, xk, nAct4);
    cvt16<<<(nAct4 + 255) / 256, 256>>>((const float4*)v_in, xv, nAct4);
    cvt16<<<(nW4 + 255) / 256, 256>>>((const float4*)wq, w_q, nW4);
    cvt16<<<(nW4 + 255) / 256, 256>>>((const float4*)wk, w_k, nW4);
    cvt16<<<(nW4 + 255) / 256, 256>>>((const float4*)wv, w_v, nW4);
    cvt16<<<(nW4 + 255) / 256, 256>>>((const float4*)wo, w_o, nW4);

    // 2. Projections (M=4096, N=768, K=768)
    dim3 gproj(MM / 128, DD / 128);
    constexpr int GSM = 2 * (128 * 80 + 128 * 80);   // 40960
    wgemm<128><<<gproj, 256, GSM>>>(xq, DD, w_q, DD, DD, 1.f, bq, 1, nullptr, Q, 0);
    wgemm<128><<<gproj, 256, GSM>>>(xk, DD, w_k, DD, DD, 1.f, bk, 1, nullptr, K, 0);
    wgemm<128><<<gproj, 256, GSM>>>(xv, DD, w_v, DD, DD, 1.f, bv, 2, nullptr, Vt, 0);

    // 3. Fused attention (scores + softmax + PV)
    fused_attn<<<dim3(SS / 128, BH), 256, FA_SMEM>>>();

    // 4. Output projection into d_out (M=4096, N=768, K=768)
    wgemm<128><<<gproj, 256, GSM>>>(O, DD, w_o, DD, DD, 1.f, bo, 0, out, nullptr, DD);
}

// round 6
// speedup vs baseline: 6.5473x; 1.0940x over previous
#include <cuda_runtime.h>
#include <cuda_fp16.h>
#include <cstdint>

// ─────────────────────────────────────────────────────────────────────────────
// Dims
// ─────────────────────────────────────────────────────────────────────────────
#define BB 2
#define SS 2048
#define DD 768
#define HH 12
#define DK 64
#define BH 24           // BB*HH
#define MM 4096         // BB*SS

#define QSCALE 0.18033688f   // 0.125 * log2(e)

// ─────────────────────────────────────────────────────────────────────────────
// Scratch (static device globals — no allocation). Single fp16 plane each.
// ─────────────────────────────────────────────────────────────────────────────
__device__ __half g_xq[MM * DD], g_xk[MM * DD], g_xv[MM * DD];
__device__ __half g_wq[DD * DD], g_wk[DD * DD], g_wv[DD * DD], g_wo[DD * DD];
__device__ __half g_Q[BH * SS * DK];     // pre-scaled by 0.125*log2e
__device__ __half g_K[BH * SS * DK];
__device__ __half g_Vt[BH * SS * DK];    // [bh, dk, s]
__device__ __half g_O[MM * DD];          // merged heads [B*S, D]

// ─────────────────────────────────────────────────────────────────────────────
// PTX helpers (baseline ISA only — harness targets sm_103 non-'a', no tcgen05)
// ─────────────────────────────────────────────────────────────────────────────
__device__ __forceinline__ uint32_t smem_u32(const void* p) {
    uint32_t a;
    asm("{ .reg .u64 t; cvta.to.shared.u64 t, %1; cvt.u32.u64 %0, t; }"
        : "=r"(a) : "l"(p));
    return a;
}

__device__ __forceinline__ void cp_async16(uint32_t saddr, const void* gaddr) {
    asm volatile("cp.async.ca.shared.global [%0], [%1], 16;"
                 :: "r"(saddr), "l"(gaddr));
}
__device__ __forceinline__ void cp_commit() {
    asm volatile("cp.async.commit_group;");
}
__device__ __forceinline__ void cp_wait_all() {
    asm volatile("cp.async.wait_group 0;");
}
__device__ __forceinline__ void cp_wait_1() {
    asm volatile("cp.async.wait_group 1;");
}

__device__ __forceinline__ void ldm_x4(uint32_t addr, uint32_t* r) {
    asm volatile("ldmatrix.sync.aligned.m8n8.x4.shared.b16 {%0,%1,%2,%3}, [%4];"
                 : "=r"(r[0]), "=r"(r[1]), "=r"(r[2]), "=r"(r[3]) : "r"(addr));
}
__device__ __forceinline__ void ldm_x2(uint32_t addr, uint32_t* r) {
    asm volatile("ldmatrix.sync.aligned.m8n8.x2.shared.b16 {%0,%1}, [%2];"
                 : "=r"(r[0]), "=r"(r[1]) : "r"(addr));
}

// fp16 in, fp32 accumulate
__device__ __forceinline__ void mma16816(float* c, const uint32_t* a, const uint32_t* b) {
    asm volatile(
        "mma.sync.aligned.m16n8k16.row.col.f32.f16.f16.f32 "
        "{%0,%1,%2,%3}, {%4,%5,%6,%7}, {%8,%9}, {%0,%1,%2,%3};"
        : "+f"(c[0]), "+f"(c[1]), "+f"(c[2]), "+f"(c[3])
        : "r"(a[0]), "r"(a[1]), "r"(a[2]), "r"(a[3]), "r"(b[0]), "r"(b[1]));
}

__device__ __forceinline__ uint32_t pack_h2(float a, float b) {
    __half2 t = __floats2half2_rn(a, b);   // a in low half
    return *(uint32_t*)&t;
}

__device__ __forceinline__ float ex2(float x) {
    float y;
    asm("ex2.approx.f32 %0, %1;" : "=f"(y) : "f"(x));
    return y;
}

// ─────────────────────────────────────────────────────────────────────────────
// Shared GEMM mainloop body (NT, fp16, BM=128, BN=128, BK=32, 256 threads)
// Computes acc[4][4][4] for this thread. Epilogue supplied by caller.
// ─────────────────────────────────────────────────────────────────────────────
#define GEMM_LDSB  80
#define GEMM_ATILE (128 * GEMM_LDSB)
#define GEMM_STAGE (2 * GEMM_ATILE)
#define GEMM_SMEM  (2 * GEMM_STAGE)      // 40960

__device__ __forceinline__ void gemm_mainloop(
    const __half* __restrict__ pA, int lda,
    const __half* __restrict__ pB, int ldb,
    int K, uint32_t sb, int tid, float acc[4][4][4])
{
    const int w    = tid >> 5;
    const int lane = tid & 31;
    const int wm0 = (w & 1) * 64;
    const int wn0 = (w >> 1) * 32;

    auto load_stage = [&](int st, int k0) {
        const uint32_t s0 = sb + st * GEMM_STAGE;
        for (int c = tid; c < 512; c += 256) {
            const int r = c >> 2, kc = c & 3;
            cp_async16(s0 + r * GEMM_LDSB + kc * 16, pA + (size_t)r * lda + k0 + kc * 8);
            cp_async16(s0 + GEMM_ATILE + r * GEMM_LDSB + kc * 16,
                       pB + (size_t)r * ldb + k0 + kc * 8);
        }
        cp_commit();
    };

#pragma unroll
    for (int i = 0; i < 4; i++)
#pragma unroll
        for (int j = 0; j < 4; j++)
#pragma unroll
            for (int q = 0; q < 4; q++) acc[i][j][q] = 0.f;

    const int niter = K >> 5;
    load_stage(0, 0);

    for (int it = 0; it < niter; it++) {
        cp_wait_all();
        __syncthreads();
        if (it + 1 < niter) load_stage((it + 1) & 1, (it + 1) << 5);

        const uint32_t sA = sb + (it & 1) * GEMM_STAGE;
        const uint32_t sB = sA + GEMM_ATILE;

#pragma unroll
        for (int ks = 0; ks < 2; ks++) {
            uint32_t fA[4][4], fB[4][2];
            const uint32_t acol = ks * 32 + (lane >> 4) * 16;
            const uint32_t bcol = ks * 32 + ((lane >> 3) & 1) * 16;
#pragma unroll
            for (int mi = 0; mi < 4; mi++)
                ldm_x4(sA + (wm0 + mi * 16 + (lane & 15)) * GEMM_LDSB + acol, fA[mi]);
#pragma unroll
            for (int ni = 0; ni < 4; ni++)
                ldm_x2(sB + (wn0 + ni * 8 + (lane & 7)) * GEMM_LDSB + bcol, fB[ni]);
#pragma unroll
            for (int mi = 0; mi < 4; mi++)
#pragma unroll
                for (int ni = 0; ni < 4; ni++)
                    mma16816(acc[mi][ni], fA[mi], fB[ni]);
        }
        __syncthreads();
    }
}

// ─────────────────────────────────────────────────────────────────────────────
// Batched QKV projection: blockIdx.z selects {Q, K, V}.
//   C = (x @ W^T + b) * scale_z, written head-split fp16.
//   z=0 (Q): scale = 0.125*log2e, layout [bh, s, dk]
//   z=1 (K): scale = 1,           layout [bh, s, dk]
//   z=2 (V): scale = 1,           layout [bh, dk, s]  (transposed)
// ─────────────────────────────────────────────────────────────────────────────
struct QKVArgs {
    const __half* A[3];
    const __half* W[3];
    const float*  bias[3];
    __half*       C[3];
};

__global__ void __launch_bounds__(256) proj_qkv(QKVArgs args)
{
    extern __shared__ __align__(16) char smem[];
    const uint32_t sb = smem_u32(smem);
    const int tid = threadIdx.x;
    const int z = blockIdx.z;
    const int m0 = blockIdx.x * 128;
    const int n0 = blockIdx.y * 128;

    float acc[4][4][4];
    gemm_mainloop(args.A[z] + (size_t)m0 * DD, DD,
                  args.W[z] + (size_t)n0 * DD, DD, DD, sb, tid, acc);

    const float scale = (z == 0) ? QSCALE : 1.f;
    const float* bias = args.bias[z];
    __half* C = args.C[z];

    const int w = tid >> 5, lane = tid & 31;
    const int wm0 = (w & 1) * 64, wn0 = (w >> 1) * 32;
    const int qr = lane >> 2, qc = (lane & 3) * 2;
#pragma unroll
    for (int mi = 0; mi < 4; mi++)
#pragma unroll
        for (int ni = 0; ni < 4; ni++)
#pragma unroll
            for (int h2 = 0; h2 < 2; h2++) {
                const int row = m0 + wm0 + mi * 16 + qr + h2 * 8;
                const int col = n0 + wn0 + ni * 8 + qc;
                const float v0 = (acc[mi][ni][h2 * 2 + 0] + bias[col])     * scale;
                const float v1 = (acc[mi][ni][h2 * 2 + 1] + bias[col + 1]) * scale;
                const int b = row >> 11, s = row & 2047, h = col >> 6, dk = col & 63;
                if (z != 2) {
                    const size_t o = ((((size_t)b * HH + h) * SS) + s) * DK + dk;
                    *(__half2*)&C[o] = __floats2half2_rn(v0, v1);
                } else {
                    const size_t o = ((((size_t)b * HH + h) * DK) + dk) * SS + s;
                    C[o]      = __float2half_rn(v0);
                    C[o + SS] = __float2half_rn(v1);
                }
            }
}

// ─────────────────────────────────────────────────────────────────────────────
// Output projection: out = O @ Wo^T + bo, fp32 output.
// ─────────────────────────────────────────────────────────────────────────────
__global__ void __launch_bounds__(256) proj_out(
    const __half* __restrict__ A, const __half* __restrict__ W,
    const float* __restrict__ bias, float* __restrict__ Cf)
{
    extern __shared__ __align__(16) char smem[];
    const uint32_t sb = smem_u32(smem);
    const int tid = threadIdx.x;
    const int m0 = blockIdx.x * 128;
    const int n0 = blockIdx.y * 128;

    float acc[4][4][4];
    gemm_mainloop(A + (size_t)m0 * DD, DD, W + (size_t)n0 * DD, DD, DD, sb, tid, acc);

    const int w = tid >> 5, lane = tid & 31;
    const int wm0 = (w & 1) * 64, wn0 = (w >> 1) * 32;
    const int qr = lane >> 2, qc = (lane & 3) * 2;
#pragma unroll
    for (int mi = 0; mi < 4; mi++)
#pragma unroll
        for (int ni = 0; ni < 4; ni++)
#pragma unroll
            for (int h2 = 0; h2 < 2; h2++) {
                const int row = m0 + wm0 + mi * 16 + qr + h2 * 8;
                const int col = n0 + wn0 + ni * 8 + qc;
                *(float2*)&Cf[(size_t)row * DD + col] =
                    make_float2(acc[mi][ni][h2 * 2 + 0] + bias[col],
                                acc[mi][ni][h2 * 2 + 1] + bias[col + 1]);
            }
}

// ─────────────────────────────────────────────────────────────────────────────
// Fused flash attention. Q pre-scaled by 0.125*log2e -> softmax in log2 domain
// (raw ex2.approx, zero extra multiplies in the inner loop).
// ─────────────────────────────────────────────────────────────────────────────
#define BKV    64
#define LDK    144                       // 64 fp16 = 128B row + 16B pad
#define KPLANE (64 * LDK)                // 9216
#define QPLANE (128 * LDK)               // 18432
#define OFF_Q  0
#define OFF_S  QPLANE                    // 18432
#define STAGEA (2 * KPLANE)              // K + V = 18432
#define FA_SMEM (OFF_S + 2 * STAGEA)     // 55296

__global__ void __launch_bounds__(256) fused_attn()
{
    extern __shared__ __align__(16) char smem[];
    const uint32_t sb = smem_u32(smem);

    const int tid  = threadIdx.x;
    const int w    = tid >> 5;
    const int lane = tid & 31;
    const int qbase = blockIdx.x * 128;
    const int bh   = blockIdx.y;
    const int b    = bh / HH, h = bh % HH;

    const __half* pQ = g_Q  + (size_t)bh * SS * DK;
    const __half* pK = g_K  + (size_t)bh * SS * DK;
    const __half* pV = g_Vt + (size_t)bh * DK * SS;

    auto load_q = [&]() {
        for (int c = tid; c < 1024; c += 256) {
            const int r = c >> 3, kc = c & 7;
            cp_async16(sb + OFF_Q + r * LDK + kc * 16,
                       pQ + (size_t)(qbase + r) * DK + kc * 8);
        }
        cp_commit();
    };
    auto load_kv = [&](int st, int j0) {
        const uint32_t s0 = sb + OFF_S + st * STAGEA;
        for (int c = tid; c < 512; c += 256) {
            const int r = c >> 3, kc = c & 7;
            cp_async16(s0 + r * LDK + kc * 16,
                       pK + (size_t)(j0 + r) * DK + kc * 8);
            cp_async16(s0 + KPLANE + r * LDK + kc * 16,
                       pV + (size_t)r * SS + j0 + kc * 8);
        }
        cp_commit();
    };

    load_q();
    load_kv(0, 0);

    uint32_t Qf[4][4];
    float Oa[8][4];
#pragma unroll
    for (int ni = 0; ni < 8; ni++)
#pragma unroll
        for (int q = 0; q < 4; q++) Oa[ni][q] = 0.f;
    float m0 = -1e30f, m1 = -1e30f, l0 = 0.f, l1 = 0.f;

    constexpr int NSTEP = SS / BKV;   // 32
    for (int jt = 0; jt < NSTEP; jt++) {
        if (jt + 1 < NSTEP) { load_kv((jt + 1) & 1, (jt + 1) * BKV); cp_wait_1(); }
        else                { cp_wait_all(); }
        __syncthreads();

        if (jt == 0) {
#pragma unroll
            for (int ks = 0; ks < 4; ks++) {
                const uint32_t ar = (uint32_t)(w * 16 + (lane & 15)) * LDK +
                                    ks * 32 + (lane >> 4) * 16;
                ldm_x4(sb + OFF_Q + ar, Qf[ks]);
            }
        }

        const uint32_t sK = sb + OFF_S + (jt & 1) * STAGEA;
        const uint32_t sV = sK + KPLANE;

        // ---- S' = Qs K^T (already in log2 units) ----
        float Sa[8][4];
#pragma unroll
        for (int ni = 0; ni < 8; ni++)
#pragma unroll
            for (int q = 0; q < 4; q++) Sa[ni][q] = 0.f;

#pragma unroll
        for (int ks = 0; ks < 4; ks++) {
            uint32_t kf[8][2];
#pragma unroll
            for (int ni = 0; ni < 8; ni++)
                ldm_x2(sK + (uint32_t)(ni * 8 + (lane & 7)) * LDK +
                       ks * 32 + ((lane >> 3) & 1) * 16, kf[ni]);
#pragma unroll
            for (int ni = 0; ni < 8; ni++)
                mma16816(Sa[ni], Qf[ks], kf[ni]);
        }

        // ---- online softmax (log2 domain) ----
        float mx0 = -1e30f, mx1 = -1e30f;
#pragma unroll
        for (int ni = 0; ni < 8; ni++) {
            mx0 = fmaxf(mx0, fmaxf(Sa[ni][0], Sa[ni][1]));
            mx1 = fmaxf(mx1, fmaxf(Sa[ni][2], Sa[ni][3]));
        }
        mx0 = fmaxf(mx0, __shfl_xor_sync(0xffffffffu, mx0, 1));
        mx0 = fmaxf(mx0, __shfl_xor_sync(0xffffffffu, mx0, 2));
        mx1 = fmaxf(mx1, __shfl_xor_sync(0xffffffffu, mx1, 1));
        mx1 = fmaxf(mx1, __shfl_xor_sync(0xffffffffu, mx1, 2));

        const float mn0 = fmaxf(m0, mx0), mn1 = fmaxf(m1, mx1);
        const float a0 = ex2(m0 - mn0), a1 = ex2(m1 - mn1);
        m0 = mn0; m1 = mn1;

        float rs0 = 0.f, rs1 = 0.f;
#pragma unroll
        for (int ni = 0; ni < 8; ni++) {
            Sa[ni][0] = ex2(Sa[ni][0] - mn0);
            Sa[ni][1] = ex2(Sa[ni][1] - mn0);
            Sa[ni][2] = ex2(Sa[ni][2] - mn1);
            Sa[ni][3] = ex2(Sa[ni][3] - mn1);
            rs0 += Sa[ni][0] + Sa[ni][1];
            rs1 += Sa[ni][2] + Sa[ni][3];
            Oa[ni][0] *= a0; Oa[ni][1] *= a0;
            Oa[ni][2] *= a1; Oa[ni][3] *= a1;
        }
        rs0 += __shfl_xor_sync(0xffffffffu, rs0, 1);
        rs0 += __shfl_xor_sync(0xffffffffu, rs0, 2);
        rs1 += __shfl_xor_sync(0xffffffffu, rs1, 1);
        rs1 += __shfl_xor_sync(0xffffffffu, rs1, 2);
        l0 = l0 * a0 + rs0;
        l1 = l1 * a1 + rs1;

        // ---- P -> fp16 A-fragments (register remap) ----
        uint32_t pf[4][4];
#pragma unroll
        for (int t = 0; t < 4; t++) {
            pf[t][0] = pack_h2(Sa[2*t][0],   Sa[2*t][1]);
            pf[t][1] = pack_h2(Sa[2*t][2],   Sa[2*t][3]);
            pf[t][2] = pack_h2(Sa[2*t+1][0], Sa[2*t+1][1]);
            pf[t][3] = pack_h2(Sa[2*t+1][2], Sa[2*t+1][3]);
        }

        // ---- O += P V ----
#pragma unroll
        for (int t = 0; t < 4; t++) {
            uint32_t vf[8][2];
#pragma unroll
            for (int ni = 0; ni < 8; ni++)
                ldm_x2(sV + (uint32_t)(ni * 8 + (lane & 7)) * LDK +
                       t * 32 + ((lane >> 3) & 1) * 16, vf[ni]);
#pragma unroll
            for (int ni = 0; ni < 8; ni++)
                mma16816(Oa[ni], pf[t], vf[ni]);
        }
        __syncthreads();
    }

    // ---- epilogue: O /= l, write merged-head fp16 ----
    const float inv0 = 1.f / l0, inv1 = 1.f / l1;
    const int qr = lane >> 2, qc = (lane & 3) * 2;
    const int s0r = qbase + w * 16 + qr;
#pragma unroll
    for (int ni = 0; ni < 8; ni++) {
        const int col = ni * 8 + qc;
        const size_t o0 = ((size_t)(b * SS + s0r))     * DD + h * DK + col;
        const size_t o1 = ((size_t)(b * SS + s0r + 8)) * DD + h * DK + col;
        *(__half2*)&g_O[o0] = __floats2half2_rn(Oa[ni][0] * inv0, Oa[ni][1] * inv0);
        *(__half2*)&g_O[o1] = __floats2half2_rn(Oa[ni][2] * inv1, Oa[ni][3] * inv1);
    }
}

// ─────────────────────────────────────────────────────────────────────────────
// Batched fp32 -> fp16 converts (one launch for 3 acts, one for 4 weights)
// ─────────────────────────────────────────────────────────────────────────────
struct Cvt3 { const float4* s[3]; __half* d[3]; };
struct Cvt4 { const float4* s[4]; __half* d[4]; };

__global__ void __launch_bounds__(256) cvt16_acts(Cvt3 a, int n4)
{
    const int t = blockIdx.y;
    const int i = blockIdx.x * 256 + threadIdx.x;
    if (i < n4) {
        float4 v = a.s[t][i];
        __half2 x = __floats2half2_rn(v.x, v.y);
        __half2 y = __floats2half2_rn(v.z, v.w);
        *(uint2*)(a.d[t] + 4 * (size_t)i) = make_uint2(*(uint32_t*)&x, *(uint32_t*)&y);
    }
}

__global__ void __launch_bounds__(256) cvt16_wts(Cvt4 a, int n4)
{
    const int t = blockIdx.y;
    const int i = blockIdx.x * 256 + threadIdx.x;
    if (i < n4) {
        float4 v = a.s[t][i];
        __half2 x = __floats2half2_rn(v.x, v.y);
        __half2 y = __floats2half2_rn(v.z, v.w);
        *(uint2*)(a.d[t] + 4 * (size_t)i) = make_uint2(*(uint32_t*)&x, *(uint32_t*)&y);
    }
}

// ─────────────────────────────────────────────────────────────────────────────
// kernel_launch
// Input order: k, q, v, mask, wq, bq, wk, bk, wv, bv, wo, bo
// ─────────────────────────────────────────────────────────────────────────────
extern "C" void kernel_launch(void* const* d_in, const int* in_sizes, int n_in,
                              void* d_out, int out_size)
{
    const float* k_in = (const float*)d_in[0];
    const float* q_in = (const float*)d_in[1];
    const float* v_in = (const float*)d_in[2];
    const float* wq = (const float*)d_in[4];
    const float* bq = (const float*)d_in[5];
    const float* wk = (const float*)d_in[6];
    const float* bk = (const float*)d_in[7];
    const float* wv = (const float*)d_in[8];
    const float* bv = (const float*)d_in[9];
    const float* wo = (const float*)d_in[10];
    const float* bo = (const float*)d_in[11];
    float* out = (float*)d_out;

    __half *xq, *xk, *xv, *w_q, *w_k, *w_v, *w_o, *Q, *K, *Vt, *O;
    cudaGetSymbolAddress((void**)&xq, g_xq);
    cudaGetSymbolAddress((void**)&xk, g_xk);
    cudaGetSymbolAddress((void**)&xv, g_xv);
    cudaGetSymbolAddress((void**)&w_q, g_wq);
    cudaGetSymbolAddress((void**)&w_k, g_wk);
    cudaGetSymbolAddress((void**)&w_v, g_wv);
    cudaGetSymbolAddress((void**)&w_o, g_wo);
    cudaGetSymbolAddress((void**)&Q,  g_Q);
    cudaGetSymbolAddress((void**)&K,  g_K);
    cudaGetSymbolAddress((void**)&Vt, g_Vt);
    cudaGetSymbolAddress((void**)&O,  g_O);

    cudaFuncSetAttribute(fused_attn, cudaFuncAttributeMaxDynamicSharedMemorySize, FA_SMEM);

    const int nAct4 = MM * DD / 4, nW4 = DD * DD / 4;

    // 1. fp32 -> fp16 conversions (2 batched launches)
    Cvt3 ca;
    ca.s[0] = (const float4*)q_in; ca.d[0] = xq;
    ca.s[1] = (const float4*)k_in; ca.d[1] = xk;
    ca.s[2] = (const float4*)v_in; ca.d[2] = xv;
    cvt16_acts<<<dim3((nAct4 + 255) / 256, 3), 256>>>(ca, nAct4);

    Cvt4 cw;
    cw.s[0] = (const float4*)wq; cw.d[0] = w_q;
    cw.s[1] = (const float4*)wk; cw.d[1] = w_k;
    cw.s[2] = (const float4*)wv; cw.d[2] = w_v;
    cw.s[3] = (const float4*)wo; cw.d[3] = w_o;
    cvt16_wts<<<dim3((nW4 + 255) / 256, 4), 256>>>(cw, nW4);

    // 2. Batched Q/K/V projections (one launch, z = {Q,K,V})
    QKVArgs pa;
    pa.A[0] = xq;  pa.A[1] = xk;  pa.A[2] = xv;
    pa.W[0] = w_q; pa.W[1] = w_k; pa.W[2] = w_v;
    pa.bias[0] = bq; pa.bias[1] = bk; pa.bias[2] = bv;
    pa.C[0] = Q; pa.C[1] = K; pa.C[2] = Vt;
    proj_qkv<<<dim3(MM / 128, DD / 128, 3), 256, GEMM_SMEM>>>(pa);

    // 3. Fused attention (scores + softmax + PV), log2-domain softmax
    fused_attn<<<dim3(SS / 128, BH), 256, FA_SMEM>>>();

    // 4. Output projection into d_out
    proj_out<<<dim3(MM / 128, DD / 128), 256, GEMM_SMEM>>>(O, w_o, bo, out);
}

// round 7
// speedup vs baseline: 7.0214x; 1.0724x over previous
#include <cuda_runtime.h>
#include <cuda_fp16.h>
#include <cstdint>

// ─────────────────────────────────────────────────────────────────────────────
// Dims
// ─────────────────────────────────────────────────────────────────────────────
#define BB 2
#define SS 2048
#define DD 768
#define HH 12
#define DK 64
#define BH 24           // BB*HH
#define MM 4096         // BB*SS

#define QSCALE 0.18033688f   // 0.125 * log2(e)

// ─────────────────────────────────────────────────────────────────────────────
// Scratch (static device globals — no allocation). Single fp16 plane each.
// ─────────────────────────────────────────────────────────────────────────────
__device__ __half g_xq[MM * DD], g_xk[MM * DD], g_xv[MM * DD];
__device__ __half g_wq[DD * DD], g_wk[DD * DD], g_wv[DD * DD], g_wo[DD * DD];
__device__ __half g_Q[BH * SS * DK];     // pre-scaled by 0.125*log2e
__device__ __half g_K[BH * SS * DK];
__device__ __half g_Vt[BH * SS * DK];    // [bh, dk, s]
__device__ __half g_O[MM * DD];          // merged heads [B*S, D]

// ─────────────────────────────────────────────────────────────────────────────
// PTX helpers (baseline ISA only — harness targets sm_103 non-'a', no tcgen05)
// ─────────────────────────────────────────────────────────────────────────────
__device__ __forceinline__ uint32_t smem_u32(const void* p) {
    uint32_t a;
    asm("{ .reg .u64 t; cvta.to.shared.u64 t, %1; cvt.u32.u64 %0, t; }"
        : "=r"(a) : "l"(p));
    return a;
}

__device__ __forceinline__ void cp_async16(uint32_t saddr, const void* gaddr) {
    asm volatile("cp.async.ca.shared.global [%0], [%1], 16;"
                 :: "r"(saddr), "l"(gaddr));
}
__device__ __forceinline__ void cp_commit() {
    asm volatile("cp.async.commit_group;");
}
__device__ __forceinline__ void cp_wait_all() {
    asm volatile("cp.async.wait_group 0;");
}
__device__ __forceinline__ void cp_wait_1() {
    asm volatile("cp.async.wait_group 1;");
}

__device__ __forceinline__ void ldm_x4(uint32_t addr, uint32_t* r) {
    asm volatile("ldmatrix.sync.aligned.m8n8.x4.shared.b16 {%0,%1,%2,%3}, [%4];"
                 : "=r"(r[0]), "=r"(r[1]), "=r"(r[2]), "=r"(r[3]) : "r"(addr));
}

// fp16 in, fp32 accumulate
__device__ __forceinline__ void mma16816(float* c, const uint32_t* a, const uint32_t* b) {
    asm volatile(
        "mma.sync.aligned.m16n8k16.row.col.f32.f16.f16.f32 "
        "{%0,%1,%2,%3}, {%4,%5,%6,%7}, {%8,%9}, {%0,%1,%2,%3};"
        : "+f"(c[0]), "+f"(c[1]), "+f"(c[2]), "+f"(c[3])
        : "r"(a[0]), "r"(a[1]), "r"(a[2]), "r"(a[3]), "r"(b[0]), "r"(b[1]));
}

__device__ __forceinline__ uint32_t pack_h2(float a, float b) {
    __half2 t = __floats2half2_rn(a, b);   // a in low half
    return *(uint32_t*)&t;
}

__device__ __forceinline__ float ex2(float x) {
    float y;
    asm("ex2.approx.f32 %0, %1;" : "=f"(y) : "f"(x));
    return y;
}

// ─────────────────────────────────────────────────────────────────────────────
// Shared GEMM mainloop body (NT, fp16, BM=128, BN=128, BK=32, 256 threads)
// B fragments loaded pairwise via ldm_x4.
// ─────────────────────────────────────────────────────────────────────────────
#define GEMM_LDSB  80
#define GEMM_ATILE (128 * GEMM_LDSB)
#define GEMM_STAGE (2 * GEMM_ATILE)
#define GEMM_SMEM  (2 * GEMM_STAGE)      // 40960

__device__ __forceinline__ void gemm_mainloop(
    const __half* __restrict__ pA, int lda,
    const __half* __restrict__ pB, int ldb,
    int K, uint32_t sb, int tid, float acc[4][4][4])
{
    const int w    = tid >> 5;
    const int lane = tid & 31;
    const int wm0 = (w & 1) * 64;
    const int wn0 = (w >> 1) * 32;

    auto load_stage = [&](int st, int k0) {
        const uint32_t s0 = sb + st * GEMM_STAGE;
        for (int c = tid; c < 512; c += 256) {
            const int r = c >> 2, kc = c & 3;
            cp_async16(s0 + r * GEMM_LDSB + kc * 16, pA + (size_t)r * lda + k0 + kc * 8);
            cp_async16(s0 + GEMM_ATILE + r * GEMM_LDSB + kc * 16,
                       pB + (size_t)r * ldb + k0 + kc * 8);
        }
        cp_commit();
    };

#pragma unroll
    for (int i = 0; i < 4; i++)
#pragma unroll
        for (int j = 0; j < 4; j++)
#pragma unroll
            for (int q = 0; q < 4; q++) acc[i][j][q] = 0.f;

    const int niter = K >> 5;
    load_stage(0, 0);

    for (int it = 0; it < niter; it++) {
        cp_wait_all();
        __syncthreads();
        if (it + 1 < niter) load_stage((it + 1) & 1, (it + 1) << 5);

        const uint32_t sA = sb + (it & 1) * GEMM_STAGE;
        const uint32_t sB = sA + GEMM_ATILE;

#pragma unroll
        for (int ks = 0; ks < 2; ks++) {
            uint32_t fA[4][4], fB[2][4];
            const uint32_t acol = ks * 32 + (lane >> 4) * 16;
            const uint32_t bcol = ks * 32 + ((lane >> 3) & 1) * 16;
            const uint32_t brow = ((lane >> 4) & 1) * 8 + (lane & 7);
#pragma unroll
            for (int mi = 0; mi < 4; mi++)
                ldm_x4(sA + (wm0 + mi * 16 + (lane & 15)) * GEMM_LDSB + acol, fA[mi]);
#pragma unroll
            for (int np = 0; np < 2; np++)
                ldm_x4(sB + (wn0 + np * 16 + brow) * GEMM_LDSB + bcol, fB[np]);
#pragma unroll
            for (int mi = 0; mi < 4; mi++)
#pragma unroll
                for (int np = 0; np < 2; np++) {
                    mma16816(acc[mi][2 * np],     fA[mi], fB[np]);
                    mma16816(acc[mi][2 * np + 1], fA[mi], fB[np] + 2);
                }
        }
        __syncthreads();
    }
}

// ─────────────────────────────────────────────────────────────────────────────
// Batched QKV projection: blockIdx.z selects {Q, K, V}.
// ─────────────────────────────────────────────────────────────────────────────
struct QKVArgs {
    const __half* A[3];
    const __half* W[3];
    const float*  bias[3];
    __half*       C[3];
};

__global__ void __launch_bounds__(256) proj_qkv(QKVArgs args)
{
    extern __shared__ __align__(16) char smem[];
    const uint32_t sb = smem_u32(smem);
    const int tid = threadIdx.x;
    const int z = blockIdx.z;
    const int m0 = blockIdx.x * 128;
    const int n0 = blockIdx.y * 128;

    float acc[4][4][4];
    gemm_mainloop(args.A[z] + (size_t)m0 * DD, DD,
                  args.W[z] + (size_t)n0 * DD, DD, DD, sb, tid, acc);

    const float scale = (z == 0) ? QSCALE : 1.f;
    const float* bias = args.bias[z];
    __half* C = args.C[z];

    const int w = tid >> 5, lane = tid & 31;
    const int wm0 = (w & 1) * 64, wn0 = (w >> 1) * 32;
    const int qr = lane >> 2, qc = (lane & 3) * 2;
#pragma unroll
    for (int mi = 0; mi < 4; mi++)
#pragma unroll
        for (int ni = 0; ni < 4; ni++)
#pragma unroll
            for (int h2 = 0; h2 < 2; h2++) {
                const int row = m0 + wm0 + mi * 16 + qr + h2 * 8;
                const int col = n0 + wn0 + ni * 8 + qc;
                const float v0 = (acc[mi][ni][h2 * 2 + 0] + bias[col])     * scale;
                const float v1 = (acc[mi][ni][h2 * 2 + 1] + bias[col + 1]) * scale;
                const int b = row >> 11, s = row & 2047, h = col >> 6, dk = col & 63;
                if (z != 2) {
                    const size_t o = ((((size_t)b * HH + h) * SS) + s) * DK + dk;
                    *(__half2*)&C[o] = __floats2half2_rn(v0, v1);
                } else {
                    const size_t o = ((((size_t)b * HH + h) * DK) + dk) * SS + s;
                    C[o]      = __float2half_rn(v0);
                    C[o + SS] = __float2half_rn(v1);
                }
            }
}

// ─────────────────────────────────────────────────────────────────────────────
// Output projection: out = O @ Wo^T + bo, fp32 output.
// ─────────────────────────────────────────────────────────────────────────────
__global__ void __launch_bounds__(256) proj_out(
    const __half* __restrict__ A, const __half* __restrict__ W,
    const float* __restrict__ bias, float* __restrict__ Cf)
{
    extern __shared__ __align__(16) char smem[];
    const uint32_t sb = smem_u32(smem);
    const int tid = threadIdx.x;
    const int m0 = blockIdx.x * 128;
    const int n0 = blockIdx.y * 128;

    float acc[4][4][4];
    gemm_mainloop(A + (size_t)m0 * DD, DD, W + (size_t)n0 * DD, DD, DD, sb, tid, acc);

    const int w = tid >> 5, lane = tid & 31;
    const int wm0 = (w & 1) * 64, wn0 = (w >> 1) * 32;
    const int qr = lane >> 2, qc = (lane & 3) * 2;
#pragma unroll
    for (int mi = 0; mi < 4; mi++)
#pragma unroll
        for (int ni = 0; ni < 4; ni++)
#pragma unroll
            for (int h2 = 0; h2 < 2; h2++) {
                const int row = m0 + wm0 + mi * 16 + qr + h2 * 8;
                const int col = n0 + wn0 + ni * 8 + qc;
                *(float2*)&Cf[(size_t)row * DD + col] =
                    make_float2(acc[mi][ni][h2 * 2 + 0] + bias[col],
                                acc[mi][ni][h2 * 2 + 1] + bias[col + 1]);
            }
}

// ─────────────────────────────────────────────────────────────────────────────
// Fused flash attention. Q pre-scaled by 0.125*log2e -> softmax in log2 domain.
// Round 7: ldm_x4 paired B loads, Q fragments reloaded per ks (regs freed),
// __launch_bounds__(256, 3) targeting 3 CTAs/SM (single wave at grid=384).
// ─────────────────────────────────────────────────────────────────────────────
#define BKV    64
#define LDK    144                       // 64 fp16 = 128B row + 16B pad
#define KPLANE (64 * LDK)                // 9216
#define QPLANE (128 * LDK)               // 18432
#define OFF_Q  0
#define OFF_S  QPLANE                    // 18432
#define STAGEA (2 * KPLANE)              // K + V = 18432
#define FA_SMEM (OFF_S + 2 * STAGEA)     // 55296

__global__ void __launch_bounds__(256, 3) fused_attn()
{
    extern __shared__ __align__(16) char smem[];
    const uint32_t sb = smem_u32(smem);

    const int tid  = threadIdx.x;
    const int w    = tid >> 5;
    const int lane = tid & 31;
    const int qbase = blockIdx.x * 128;
    const int bh   = blockIdx.y;
    const int b    = bh / HH, h = bh % HH;

    const __half* pQ = g_Q  + (size_t)bh * SS * DK;
    const __half* pK = g_K  + (size_t)bh * SS * DK;
    const __half* pV = g_Vt + (size_t)bh * DK * SS;

    auto load_q = [&]() {
        for (int c = tid; c < 1024; c += 256) {
            const int r = c >> 3, kc = c & 7;
            cp_async16(sb + OFF_Q + r * LDK + kc * 16,
                       pQ + (size_t)(qbase + r) * DK + kc * 8);
        }
        cp_commit();
    };
    auto load_kv = [&](int st, int j0) {
        const uint32_t s0 = sb + OFF_S + st * STAGEA;
        for (int c = tid; c < 512; c += 256) {
            const int r = c >> 3, kc = c & 7;
            cp_async16(s0 + r * LDK + kc * 16,
                       pK + (size_t)(j0 + r) * DK + kc * 8);
            cp_async16(s0 + KPLANE + r * LDK + kc * 16,
                       pV + (size_t)r * SS + j0 + kc * 8);
        }
        cp_commit();
    };

    load_q();
    load_kv(0, 0);

    float Oa[8][4];
#pragma unroll
    for (int ni = 0; ni < 8; ni++)
#pragma unroll
        for (int q = 0; q < 4; q++) Oa[ni][q] = 0.f;
    float m0 = -1e30f, m1 = -1e30f, l0 = 0.f, l1 = 0.f;

    // B-side ldm_x4 lane geometry (two n8 tiles per instruction)
    const uint32_t brow = ((lane >> 4) & 1) * 8 + (lane & 7);
    const uint32_t bcsel = ((lane >> 3) & 1) * 16;
    // A-side (Q) geometry
    const uint32_t arow = (uint32_t)(w * 16 + (lane & 15)) * LDK;
    const uint32_t acsel = (lane >> 4) * 16;

    constexpr int NSTEP = SS / BKV;   // 32
    for (int jt = 0; jt < NSTEP; jt++) {
        if (jt + 1 < NSTEP) { load_kv((jt + 1) & 1, (jt + 1) * BKV); cp_wait_1(); }
        else                { cp_wait_all(); }
        __syncthreads();

        const uint32_t sK = sb + OFF_S + (jt & 1) * STAGEA;
        const uint32_t sV = sK + KPLANE;

        // ---- S' = Qs K^T (log2 units) ----
        float Sa[8][4];
#pragma unroll
        for (int ni = 0; ni < 8; ni++)
#pragma unroll
            for (int q = 0; q < 4; q++) Sa[ni][q] = 0.f;

#pragma unroll
        for (int ks = 0; ks < 4; ks++) {
            uint32_t Qf[4];
            ldm_x4(sb + OFF_Q + arow + ks * 32 + acsel, Qf);
#pragma unroll
            for (int np = 0; np < 4; np++) {
                uint32_t bf[4];
                ldm_x4(sK + (uint32_t)(np * 16 + brow) * LDK + ks * 32 + bcsel, bf);
                mma16816(Sa[2 * np],     Qf, bf);
                mma16816(Sa[2 * np + 1], Qf, bf + 2);
            }
        }

        // ---- online softmax (log2 domain) ----
        float mx0 = -1e30f, mx1 = -1e30f;
#pragma unroll
        for (int ni = 0; ni < 8; ni++) {
            mx0 = fmaxf(mx0, fmaxf(Sa[ni][0], Sa[ni][1]));
            mx1 = fmaxf(mx1, fmaxf(Sa[ni][2], Sa[ni][3]));
        }
        mx0 = fmaxf(mx0, __shfl_xor_sync(0xffffffffu, mx0, 1));
        mx0 = fmaxf(mx0, __shfl_xor_sync(0xffffffffu, mx0, 2));
        mx1 = fmaxf(mx1, __shfl_xor_sync(0xffffffffu, mx1, 1));
        mx1 = fmaxf(mx1, __shfl_xor_sync(0xffffffffu, mx1, 2));

        const float mn0 = fmaxf(m0, mx0), mn1 = fmaxf(m1, mx1);
        const float a0 = ex2(m0 - mn0), a1 = ex2(m1 - mn1);
        m0 = mn0; m1 = mn1;

        float rs0 = 0.f, rs1 = 0.f;
#pragma unroll
        for (int ni = 0; ni < 8; ni++) {
            Sa[ni][0] = ex2(Sa[ni][0] - mn0);
            Sa[ni][1] = ex2(Sa[ni][1] - mn0);
            Sa[ni][2] = ex2(Sa[ni][2] - mn1);
            Sa[ni][3] = ex2(Sa[ni][3] - mn1);
            rs0 += Sa[ni][0] + Sa[ni][1];
            rs1 += Sa[ni][2] + Sa[ni][3];
            Oa[ni][0] *= a0; Oa[ni][1] *= a0;
            Oa[ni][2] *= a1; Oa[ni][3] *= a1;
        }
        rs0 += __shfl_xor_sync(0xffffffffu, rs0, 1);
        rs0 += __shfl_xor_sync(0xffffffffu, rs0, 2);
        rs1 += __shfl_xor_sync(0xffffffffu, rs1, 1);
        rs1 += __shfl_xor_sync(0xffffffffu, rs1, 2);
        l0 = l0 * a0 + rs0;
        l1 = l1 * a1 + rs1;

        // ---- P -> fp16 A-fragments (register remap, Sa dies here) ----
        uint32_t pf[4][4];
#pragma unroll
        for (int t = 0; t < 4; t++) {
            pf[t][0] = pack_h2(Sa[2*t][0],   Sa[2*t][1]);
            pf[t][1] = pack_h2(Sa[2*t][2],   Sa[2*t][3]);
            pf[t][2] = pack_h2(Sa[2*t+1][0], Sa[2*t+1][1]);
            pf[t][3] = pack_h2(Sa[2*t+1][2], Sa[2*t+1][3]);
        }

        // ---- O += P V ----
#pragma unroll
        for (int t = 0; t < 4; t++) {
#pragma unroll
            for (int np = 0; np < 4; np++) {
                uint32_t vf[4];
                ldm_x4(sV + (uint32_t)(np * 16 + brow) * LDK + t * 32 + bcsel, vf);
                mma16816(Oa[2 * np],     pf[t], vf);
                mma16816(Oa[2 * np + 1], pf[t], vf + 2);
            }
        }
        __syncthreads();
    }

    // ---- epilogue: O /= l, write merged-head fp16 ----
    const float inv0 = 1.f / l0, inv1 = 1.f / l1;
    const int qr = lane >> 2, qc = (lane & 3) * 2;
    const int s0r = qbase + w * 16 + qr;
#pragma unroll
    for (int ni = 0; ni < 8; ni++) {
        const int col = ni * 8 + qc;
        const size_t o0 = ((size_t)(b * SS + s0r))     * DD + h * DK + col;
        const size_t o1 = ((size_t)(b * SS + s0r + 8)) * DD + h * DK + col;
        *(__half2*)&g_O[o0] = __floats2half2_rn(Oa[ni][0] * inv0, Oa[ni][1] * inv0);
        *(__half2*)&g_O[o1] = __floats2half2_rn(Oa[ni][2] * inv1, Oa[ni][3] * inv1);
    }
}

// ─────────────────────────────────────────────────────────────────────────────
// Batched fp32 -> fp16 converts
// ─────────────────────────────────────────────────────────────────────────────
struct Cvt3 { const float4* s[3]; __half* d[3]; };
struct Cvt4 { const float4* s[4]; __half* d[4]; };

__global__ void __launch_bounds__(256) cvt16_acts(Cvt3 a, int n4)
{
    const int t = blockIdx.y;
    const int i = blockIdx.x * 256 + threadIdx.x;
    if (i < n4) {
        float4 v = a.s[t][i];
        __half2 x = __floats2half2_rn(v.x, v.y);
        __half2 y = __floats2half2_rn(v.z, v.w);
        *(uint2*)(a.d[t] + 4 * (size_t)i) = make_uint2(*(uint32_t*)&x, *(uint32_t*)&y);
    }
}

__global__ void __launch_bounds__(256) cvt16_wts(Cvt4 a, int n4)
{
    const int t = blockIdx.y;
    const int i = blockIdx.x * 256 + threadIdx.x;
    if (i < n4) {
        float4 v = a.s[t][i];
        __half2 x = __floats2half2_rn(v.x, v.y);
        __half2 y = __floats2half2_rn(v.z, v.w);
        *(uint2*)(a.d[t] + 4 * (size_t)i) = make_uint2(*(uint32_t*)&x, *(uint32_t*)&y);
    }
}

// ─────────────────────────────────────────────────────────────────────────────
// kernel_launch
// Input order: k, q, v, mask, wq, bq, wk, bk, wv, bv, wo, bo
// ─────────────────────────────────────────────────────────────────────────────
extern "C" void kernel_launch(void* const* d_in, const int* in_sizes, int n_in,
                              void* d_out, int out_size)
{
    const float* k_in = (const float*)d_in[0];
    const float* q_in = (const float*)d_in[1];
    const float* v_in = (const float*)d_in[2];
    const float* wq = (const float*)d_in[4];
    const float* bq = (const float*)d_in[5];
    const float* wk = (const float*)d_in[6];
    const float* bk = (const float*)d_in[7];
    const float* wv = (const float*)d_in[8];
    const float* bv = (const float*)d_in[9];
    const float* wo = (const float*)d_in[10];
    const float* bo = (const float*)d_in[11];
    float* out = (float*)d_out;

    __half *xq, *xk, *xv, *w_q, *w_k, *w_v, *w_o, *Q, *K, *Vt, *O;
    cudaGetSymbolAddress((void**)&xq, g_xq);
    cudaGetSymbolAddress((void**)&xk, g_xk);
    cudaGetSymbolAddress((void**)&xv, g_xv);
    cudaGetSymbolAddress((void**)&w_q, g_wq);
    cudaGetSymbolAddress((void**)&w_k, g_wk);
    cudaGetSymbolAddress((void**)&w_v, g_wv);
    cudaGetSymbolAddress((void**)&w_o, g_wo);
    cudaGetSymbolAddress((void**)&Q,  g_Q);
    cudaGetSymbolAddress((void**)&K,  g_K);
    cudaGetSymbolAddress((void**)&Vt, g_Vt);
    cudaGetSymbolAddress((void**)&O,  g_O);

    cudaFuncSetAttribute(fused_attn, cudaFuncAttributeMaxDynamicSharedMemorySize, FA_SMEM);

    const int nAct4 = MM * DD / 4, nW4 = DD * DD / 4;

    // 1. fp32 -> fp16 conversions (2 batched launches)
    Cvt3 ca;
    ca.s[0] = (const float4*)q_in; ca.d[0] = xq;
    ca.s[1] = (const float4*)k_in; ca.d[1] = xk;
    ca.s[2] = (const float4*)v_in; ca.d[2] = xv;
    cvt16_acts<<<dim3((nAct4 + 255) / 256, 3), 256>>>(ca, nAct4);

    Cvt4 cw;
    cw.s[0] = (const float4*)wq; cw.d[0] = w_q;
    cw.s[1] = (const float4*)wk; cw.d[1] = w_k;
    cw.s[2] = (const float4*)wv; cw.d[2] = w_v;
    cw.s[3] = (const float4*)wo; cw.d[3] = w_o;
    cvt16_wts<<<dim3((nW4 + 255) / 256, 4), 256>>>(cw, nW4);

    // 2. Batched Q/K/V projections (one launch, z = {Q,K,V})
    QKVArgs pa;
    pa.A[0] = xq;  pa.A[1] = xk;  pa.A[2] = xv;
    pa.W[0] = w_q; pa.W[1] = w_k; pa.W[2] = w_v;
    pa.bias[0] = bq; pa.bias[1] = bk; pa.bias[2] = bv;
    pa.C[0] = Q; pa.C[1] = K; pa.C[2] = Vt;
    proj_qkv<<<dim3(MM / 128, DD / 128, 3), 256, GEMM_SMEM>>>(pa);

    // 3. Fused attention (scores + softmax + PV), log2-domain softmax
    fused_attn<<<dim3(SS / 128, BH), 256, FA_SMEM>>>();

    // 4. Output projection into d_out
    proj_out<<<dim3(MM / 128, DD / 128), 256, GEMM_SMEM>>>(O, w_o, bo, out);
}